// round 1
// baseline (speedup 1.0000x reference)
#include <cuda_runtime.h>
#include <math.h>
#include <stdint.h>

#define NN 50000
#define NE 800000
#define DD 128
#define ND (NN * DD)
#define ET (NE + NN)   // edges + self loops
#define EPSF 1e-5f
#define NEGS 0.2f

// ---------------- scratch (static device globals; no allocation) ----------------
__device__ float g_h[ND];       // current node features
__device__ float g_xw[ND];      // GCN x@W
__device__ float g_xl[ND];      // GAT left transform
__device__ float g_xr[ND];      // GAT right transform
__device__ float g_acc[ND];     // aggregation output
__device__ float g_dinv[NN];    // deg^{-1/2} (also used as deg accumulator)
__device__ float g_score[ET * 8];  // per-edge per-head scores / exp weights
__device__ float g_smax[NN * 8];
__device__ float g_den[NN * 8];
__device__ double g_red[2];     // sum, sumsq for LayerNorm

// ---------------- helpers ----------------
__device__ __forceinline__ void atomicMaxF(float* addr, float val) {
    int old = __float_as_int(*addr);
    while (__int_as_float(old) < val) {
        int prev = atomicCAS((int*)addr, old, __float_as_int(val));
        if (prev == old) break;
        old = prev;
    }
}

__device__ __forceinline__ float leaky(float v) {
    return v > 0.0f ? v : NEGS * v;
}

// ---------------- degree ----------------
__global__ void k_deg_init() {
    int i = blockIdx.x * blockDim.x + threadIdx.x;
    if (i < NN) g_dinv[i] = 1.0f;   // self loop counts 1
}
__global__ void k_deg_count(const int* __restrict__ dst) {
    int e = blockIdx.x * blockDim.x + threadIdx.x;
    if (e < NE) atomicAdd(&g_dinv[dst[e]], 1.0f);
}
__global__ void k_deg_fin() {
    int i = blockIdx.x * blockDim.x + threadIdx.x;
    if (i < NN) g_dinv[i] = rsqrtf(g_dinv[i]);
}

// ---------------- GEMM: out[N,128] = A[N,128] @ W[128,128] (+bias) ----------------
__global__ void gemm128(const float* __restrict__ A, const float* __restrict__ W,
                        const float* __restrict__ bias, float* __restrict__ out) {
    __shared__ float As[32][136];   // transposed A tile, padded (16B-aligned rows)
    __shared__ float Ws[32][128];
    int t = threadIdx.x;
    int tx = t & 15, ty = t >> 4;
    int row0 = blockIdx.x * 128;

    float acc[8][8];
#pragma unroll
    for (int i = 0; i < 8; i++)
#pragma unroll
        for (int j = 0; j < 8; j++) acc[i][j] = 0.0f;

    for (int kt = 0; kt < 4; kt++) {
        int k0 = kt * 32;
        // load A tile (128 rows x 32 k) transposed into As[k][r]
#pragma unroll
        for (int j = 0; j < 4; j++) {
            int l = t + j * 256;      // float4 index 0..1023
            int lin = l * 4;
            int r = lin >> 5;         // 0..127
            int k = lin & 31;
            float4 v = make_float4(0.f, 0.f, 0.f, 0.f);
            int gr = row0 + r;
            if (gr < NN) v = *(const float4*)(A + (size_t)gr * 128 + k0 + k);
            As[k + 0][r] = v.x; As[k + 1][r] = v.y;
            As[k + 2][r] = v.z; As[k + 3][r] = v.w;
        }
        // load W tile (32 k x 128 cols), coalesced
#pragma unroll
        for (int j = 0; j < 4; j++) {
            int l = t + j * 256;
            int lin = l * 4;
            int k = lin >> 7;
            int c = lin & 127;
            *(float4*)&Ws[k][c] = *(const float4*)(W + (size_t)(k0 + k) * 128 + c);
        }
        __syncthreads();
#pragma unroll
        for (int k = 0; k < 32; k++) {
            float a[8], b[8];
            *(float4*)(a)     = *(float4*)&As[k][ty * 8];
            *(float4*)(a + 4) = *(float4*)&As[k][ty * 8 + 4];
            *(float4*)(b)     = *(float4*)&Ws[k][tx * 8];
            *(float4*)(b + 4) = *(float4*)&Ws[k][tx * 8 + 4];
#pragma unroll
            for (int i = 0; i < 8; i++)
#pragma unroll
                for (int j = 0; j < 8; j++) acc[i][j] += a[i] * b[j];
        }
        __syncthreads();
    }
#pragma unroll
    for (int i = 0; i < 8; i++) {
        int gr = row0 + ty * 8 + i;
        if (gr >= NN) continue;
        float* o = out + (size_t)gr * 128 + tx * 8;
        float4 v0, v1;
        if (bias) {
            v0 = make_float4(acc[i][0] + bias[tx * 8 + 0], acc[i][1] + bias[tx * 8 + 1],
                             acc[i][2] + bias[tx * 8 + 2], acc[i][3] + bias[tx * 8 + 3]);
            v1 = make_float4(acc[i][4] + bias[tx * 8 + 4], acc[i][5] + bias[tx * 8 + 5],
                             acc[i][6] + bias[tx * 8 + 6], acc[i][7] + bias[tx * 8 + 7]);
        } else {
            v0 = make_float4(acc[i][0], acc[i][1], acc[i][2], acc[i][3]);
            v1 = make_float4(acc[i][4], acc[i][5], acc[i][6], acc[i][7]);
        }
        *(float4*)(o)     = v0;
        *(float4*)(o + 4) = v1;
    }
}

// ---------------- GCN aggregation ----------------
// init: out[i] = xw[i] * dinv[row]^2   (the self-loop term, atomic-free)
__global__ void k_gcn_init() {
    int i = blockIdx.x * blockDim.x + threadIdx.x;
    if (i >= ND) return;
    float dv = g_dinv[i >> 7];
    g_acc[i] = g_xw[i] * dv * dv;
}
// one warp per edge: out[dst] += xw[src] * dinv[src]*dinv[dst]
__global__ void k_gcn_agg(const int* __restrict__ src, const int* __restrict__ dst) {
    int w = (blockIdx.x * blockDim.x + threadIdx.x) >> 5;
    int lane = threadIdx.x & 31;
    if (w >= NE) return;
    int s = src[w], d = dst[w];
    float nrm = g_dinv[s] * g_dinv[d];
    float4 v = *((const float4*)(g_xw + (size_t)s * 128) + lane);
    float* o = g_acc + (size_t)d * 128 + lane * 4;
    atomicAdd(o + 0, v.x * nrm);
    atomicAdd(o + 1, v.y * nrm);
    atomicAdd(o + 2, v.z * nrm);
    atomicAdd(o + 3, v.w * nrm);
}

// ---------------- graph LayerNorm ----------------
__global__ void k_ln_zero() { g_red[0] = 0.0; g_red[1] = 0.0; }

__global__ void k_ln_reduce(const float* __restrict__ in, const float* __restrict__ bias) {
    double s = 0.0, s2 = 0.0;
    for (int i = blockIdx.x * blockDim.x + threadIdx.x; i < ND; i += gridDim.x * blockDim.x) {
        double v = (double)(in[i] + bias[i & 127]);
        s += v; s2 += v * v;
    }
#pragma unroll
    for (int o = 16; o; o >>= 1) {
        s  += __shfl_down_sync(0xffffffffu, s, o);
        s2 += __shfl_down_sync(0xffffffffu, s2, o);
    }
    __shared__ double sh0[8], sh1[8];
    int w = threadIdx.x >> 5, l = threadIdx.x & 31;
    if (!l) { sh0[w] = s; sh1[w] = s2; }
    __syncthreads();
    if (threadIdx.x == 0) {
        double ts = 0.0, t2 = 0.0;
        int nw = blockDim.x >> 5;
        for (int i = 0; i < nw; i++) { ts += sh0[i]; t2 += sh1[i]; }
        atomicAdd(&g_red[0], ts);
        atomicAdd(&g_red[1], t2);
    }
}

template <bool RELU>
__global__ void k_ln_apply(const float* __restrict__ in, const float* __restrict__ bias,
                           const float* __restrict__ gm, const float* __restrict__ bt,
                           float* __restrict__ out) {
    int i = blockIdx.x * blockDim.x + threadIdx.x;
    if (i >= ND) return;
    double mu = g_red[0] * (1.0 / (double)ND);
    double var = g_red[1] * (1.0 / (double)ND) - mu * mu;
    float inv = 1.0f / (sqrtf(fmaxf((float)var, 0.0f)) + EPSF);
    int c = i & 127;
    float v = in[i] + bias[c];
    float r = (v - (float)mu) * inv * gm[c] + bt[c];
    if (RELU) r = fmaxf(r, 0.0f);
    out[i] = r;
}

// ---------------- GATv2 ----------------
template <int H>
__global__ void k_gat_init() {
    int i = blockIdx.x * blockDim.x + threadIdx.x;
    if (i >= ND) return;
    g_acc[i] = 0.0f;
    if (i < NN * H) { g_smax[i] = -1e30f; g_den[i] = 0.0f; }
}

// pass A: per-edge per-head score + segment max.  One warp per edge.
template <int H>
__global__ void k_gat_scores(const int* __restrict__ src, const int* __restrict__ dst,
                             const float* __restrict__ att) {
    int w = (blockIdx.x * blockDim.x + threadIdx.x) >> 5;
    int lane = threadIdx.x & 31;
    if (w >= ET) return;
    int s, d;
    if (w < NE) { s = src[w]; d = dst[w]; }
    else        { s = d = w - NE; }
    float4 l4 = *((const float4*)(g_xl + (size_t)s * 128) + lane);
    float4 r4 = *((const float4*)(g_xr + (size_t)d * 128) + lane);
    float4 a4 = *((const float4*)att + lane);   // H*C == 128 in both layers
    float p = leaky(l4.x + r4.x) * a4.x + leaky(l4.y + r4.y) * a4.y +
              leaky(l4.z + r4.z) * a4.z + leaky(l4.w + r4.w) * a4.w;
    if (H == 8) {
        // 16 channels / head -> 4 lanes / head
        p += __shfl_xor_sync(0xffffffffu, p, 1);
        p += __shfl_xor_sync(0xffffffffu, p, 2);
        if ((lane & 3) == 0) {
            int h = lane >> 2;
            g_score[(size_t)w * 8 + h] = p;
            atomicMaxF(&g_smax[d * 8 + h], p);
        }
    } else {
#pragma unroll
        for (int o = 16; o; o >>= 1) p += __shfl_xor_sync(0xffffffffu, p, o);
        if (lane == 0) {
            g_score[w] = p;
            atomicMaxF(&g_smax[d], p);
        }
    }
}

// pass B: exp(score - smax) + segment sum
template <int H>
__global__ void k_gat_exp(const int* __restrict__ dst) {
    int t = blockIdx.x * blockDim.x + threadIdx.x;
    if (t >= ET * H) return;
    int e = (H == 8) ? (t >> 3) : t;
    int h = (H == 8) ? (t & 7) : 0;
    int d = (e < NE) ? dst[e] : (e - NE);
    float a = expf(g_score[t] - g_smax[d * H + h]);
    g_score[t] = a;
    atomicAdd(&g_den[d * H + h], a);
}

// pass C: out[dst] += (a/denom) * xl[src].  One warp per edge.
template <int H>
__global__ void k_gat_agg(const int* __restrict__ src, const int* __restrict__ dst) {
    int w = (blockIdx.x * blockDim.x + threadIdx.x) >> 5;
    int lane = threadIdx.x & 31;
    if (w >= ET) return;
    int s, d;
    if (w < NE) { s = src[w]; d = dst[w]; }
    else        { s = d = w - NE; }
    float4 v = *((const float4*)(g_xl + (size_t)s * 128) + lane);
    float alpha;
    if (H == 8) {
        int h = lane >> 2;
        alpha = g_score[(size_t)w * 8 + h] / g_den[d * 8 + h];
    } else {
        alpha = g_score[w] / g_den[d];
    }
    float* o = g_acc + (size_t)d * 128 + lane * 4;
    atomicAdd(o + 0, v.x * alpha);
    atomicAdd(o + 1, v.y * alpha);
    atomicAdd(o + 2, v.z * alpha);
    atomicAdd(o + 3, v.w * alpha);
}

// ---------------- launch ----------------
static inline int gridFor(long long n, int blk) { return (int)((n + blk - 1) / blk); }

extern "C" void kernel_launch(void* const* d_in, const int* in_sizes, int n_in,
                              void* d_out, int out_size) {
    const float* x   = (const float*)d_in[0];
    const int*   ei  = (const int*)d_in[1];
    const float* W0  = (const float*)d_in[2];
    const float* b0  = (const float*)d_in[3];
    const float* g0  = (const float*)d_in[4];
    const float* be0 = (const float*)d_in[5];
    const float* Wl1 = (const float*)d_in[6];
    const float* bl1 = (const float*)d_in[7];
    const float* Wr1 = (const float*)d_in[8];
    const float* br1 = (const float*)d_in[9];
    const float* att1= (const float*)d_in[10];
    const float* bg1 = (const float*)d_in[11];
    const float* g1  = (const float*)d_in[12];
    const float* be1 = (const float*)d_in[13];
    const float* W2  = (const float*)d_in[14];
    const float* b2  = (const float*)d_in[15];
    const float* g2  = (const float*)d_in[16];
    const float* be2 = (const float*)d_in[17];
    const float* Wl3 = (const float*)d_in[18];
    const float* bl3 = (const float*)d_in[19];
    const float* Wr3 = (const float*)d_in[20];
    const float* br3 = (const float*)d_in[21];
    const float* att3= (const float*)d_in[22];
    const float* bg3 = (const float*)d_in[23];
    const float* g3  = (const float*)d_in[24];
    const float* be3 = (const float*)d_in[25];
    float* out = (float*)d_out;

    const int* src = ei;
    const int* dst = ei + NE;

    const int BLK = 256;
    const int gN   = gridFor(NN, BLK);
    const int gE   = gridFor(NE, BLK);
    const int gND  = gridFor(ND, BLK);
    const int gEW  = gridFor((long long)NE * 32, BLK);  // warp-per-edge, E
    const int gTW  = gridFor((long long)ET * 32, BLK);  // warp-per-edge, E+N
    const int gGemm = gridFor(NN, 128);

    // resolve device-global addresses
    float* p_h;   cudaGetSymbolAddress((void**)&p_h, g_h);
    float* p_xw;  cudaGetSymbolAddress((void**)&p_xw, g_xw);
    float* p_xl;  cudaGetSymbolAddress((void**)&p_xl, g_xl);
    float* p_xr;  cudaGetSymbolAddress((void**)&p_xr, g_xr);
    float* p_acc; cudaGetSymbolAddress((void**)&p_acc, g_acc);

    // degrees (with self loops)
    k_deg_init<<<gN, BLK>>>();
    k_deg_count<<<gE, BLK>>>(dst);
    k_deg_fin<<<gN, BLK>>>();

    // ---- layer 0: GCN + LN + ReLU ----
    gemm128<<<gGemm, BLK>>>(x, W0, nullptr, p_xw);
    k_gcn_init<<<gND, BLK>>>();
    k_gcn_agg<<<gEW, BLK>>>(src, dst);
    k_ln_zero<<<1, 1>>>();
    k_ln_reduce<<<1024, BLK>>>(p_acc, b0);
    k_ln_apply<true><<<gND, BLK>>>(p_acc, b0, g0, be0, p_h);

    // ---- layer 1: GATv2 (H=8) + LN + ReLU ----
    gemm128<<<gGemm, BLK>>>(p_h, Wl1, bl1, p_xl);
    gemm128<<<gGemm, BLK>>>(p_h, Wr1, br1, p_xr);
    k_gat_init<8><<<gND, BLK>>>();
    k_gat_scores<8><<<gTW, BLK>>>(src, dst, att1);
    k_gat_exp<8><<<gridFor((long long)ET * 8, BLK), BLK>>>(dst);
    k_gat_agg<8><<<gTW, BLK>>>(src, dst);
    k_ln_zero<<<1, 1>>>();
    k_ln_reduce<<<1024, BLK>>>(p_acc, bg1);
    k_ln_apply<true><<<gND, BLK>>>(p_acc, bg1, g1, be1, p_h);

    // ---- layer 2: GCN + LN + ReLU ----
    gemm128<<<gGemm, BLK>>>(p_h, W2, nullptr, p_xw);
    k_gcn_init<<<gND, BLK>>>();
    k_gcn_agg<<<gEW, BLK>>>(src, dst);
    k_ln_zero<<<1, 1>>>();
    k_ln_reduce<<<1024, BLK>>>(p_acc, b2);
    k_ln_apply<true><<<gND, BLK>>>(p_acc, b2, g2, be2, p_h);

    // ---- layer 3: GATv2 (H=1) + LN ----
    gemm128<<<gGemm, BLK>>>(p_h, Wl3, bl3, p_xl);
    gemm128<<<gGemm, BLK>>>(p_h, Wr3, br3, p_xr);
    k_gat_init<1><<<gND, BLK>>>();
    k_gat_scores<1><<<gTW, BLK>>>(src, dst, att3);
    k_gat_exp<1><<<gridFor((long long)ET, BLK), BLK>>>(dst);
    k_gat_agg<1><<<gTW, BLK>>>(src, dst);
    k_ln_zero<<<1, 1>>>();
    k_ln_reduce<<<1024, BLK>>>(p_acc, bg3);
    k_ln_apply<false><<<gND, BLK>>>(p_acc, bg3, g3, be3, out);
}

// round 3
// speedup vs baseline: 2.5098x; 2.5098x over previous
#include <cuda_runtime.h>
#include <math.h>
#include <stdint.h>

#define NN 50000
#define NE 800000
#define DD 128
#define ND (NN * DD)
#define EPSF 1e-5f
#define NEGS 0.2f

// ---------------- scratch (static device globals; no allocation) ----------------
__device__ float g_h[ND];       // current node features
__device__ float g_xw[ND];      // GCN x@W
__device__ float g_xl[ND];      // GAT left transform
__device__ float g_xr[ND];      // GAT right transform
__device__ float g_acc[ND];     // aggregation output
__device__ float g_dinv[NN];    // deg^{-1/2}
__device__ int   g_cnt[NN];     // in-degree histogram (no self loop)
__device__ int   g_off[NN + 1]; // CSR offsets
__device__ int   g_cur[NN];     // scatter cursors
__device__ int   g_csrc[NE];    // CSR: src node per incoming edge
__device__ double g_red[2];     // sum, sumsq for LayerNorm

__device__ __forceinline__ float leaky(float v) {
    return v > 0.0f ? v : NEGS * v;
}

// ---------------- CSR build ----------------
__global__ void k_hist_zero() {
    int i = blockIdx.x * blockDim.x + threadIdx.x;
    if (i < NN) g_cnt[i] = 0;
}
__global__ void k_hist(const int* __restrict__ dst) {
    int e = blockIdx.x * blockDim.x + threadIdx.x;
    if (e < NE) atomicAdd(&g_cnt[dst[e]], 1);
}
// single-block exclusive scan over g_cnt -> g_off ; also deg^{-1/2} with self loop
__global__ void k_scan() {
    __shared__ int warp_sums[32];
    __shared__ int s_base;
    int tid = threadIdx.x;
    int lane = tid & 31, wid = tid >> 5;
    if (tid == 0) s_base = 0;
    __syncthreads();
    for (int c0 = 0; c0 < NN; c0 += 1024) {
        int i = c0 + tid;
        int v = (i < NN) ? g_cnt[i] : 0;
        int x = v;
#pragma unroll
        for (int o = 1; o < 32; o <<= 1) {
            int y = __shfl_up_sync(0xffffffffu, x, o);
            if (lane >= o) x += y;
        }
        if (lane == 31) warp_sums[wid] = x;
        __syncthreads();
        if (wid == 0) {
            int ws = warp_sums[lane];
#pragma unroll
            for (int o = 1; o < 32; o <<= 1) {
                int y = __shfl_up_sync(0xffffffffu, ws, o);
                if (lane >= o) ws += y;
            }
            warp_sums[lane] = ws;
        }
        __syncthreads();
        int incl = x + (wid ? warp_sums[wid - 1] : 0);
        int base = s_base;
        int total = warp_sums[31];
        if (i < NN) {
            g_off[i] = base + incl - v;
            g_cur[i] = base + incl - v;
            g_dinv[i] = rsqrtf((float)v + 1.0f);
        }
        __syncthreads();
        if (tid == 0) s_base = base + total;
        __syncthreads();
    }
    if (tid == 0) g_off[NN] = s_base;
}
__global__ void k_scatter(const int* __restrict__ src, const int* __restrict__ dst) {
    int e = blockIdx.x * blockDim.x + threadIdx.x;
    if (e >= NE) return;
    int pos = atomicAdd(&g_cur[dst[e]], 1);
    g_csrc[pos] = src[e];
}

// ---------------- GEMM: out[N,128] = A[N,128] @ W[128,128] (+bias) ----------------
__global__ void gemm128(const float* __restrict__ A, const float* __restrict__ W,
                        const float* __restrict__ bias, float* __restrict__ out) {
    __shared__ float As[32][136];
    __shared__ float Ws[32][128];
    int t = threadIdx.x;
    int tx = t & 15, ty = t >> 4;
    int row0 = blockIdx.x * 128;

    float acc[8][8];
#pragma unroll
    for (int i = 0; i < 8; i++)
#pragma unroll
        for (int j = 0; j < 8; j++) acc[i][j] = 0.0f;

    for (int kt = 0; kt < 4; kt++) {
        int k0 = kt * 32;
#pragma unroll
        for (int j = 0; j < 4; j++) {
            int l = t + j * 256;
            int lin = l * 4;
            int r = lin >> 5;
            int k = lin & 31;
            float4 v = make_float4(0.f, 0.f, 0.f, 0.f);
            int gr = row0 + r;
            if (gr < NN) v = *(const float4*)(A + (size_t)gr * 128 + k0 + k);
            As[k + 0][r] = v.x; As[k + 1][r] = v.y;
            As[k + 2][r] = v.z; As[k + 3][r] = v.w;
        }
#pragma unroll
        for (int j = 0; j < 4; j++) {
            int l = t + j * 256;
            int lin = l * 4;
            int k = lin >> 7;
            int c = lin & 127;
            *(float4*)&Ws[k][c] = *(const float4*)(W + (size_t)(k0 + k) * 128 + c);
        }
        __syncthreads();
#pragma unroll
        for (int k = 0; k < 32; k++) {
            float a[8], b[8];
            *(float4*)(a)     = *(float4*)&As[k][ty * 8];
            *(float4*)(a + 4) = *(float4*)&As[k][ty * 8 + 4];
            *(float4*)(b)     = *(float4*)&Ws[k][tx * 8];
            *(float4*)(b + 4) = *(float4*)&Ws[k][tx * 8 + 4];
#pragma unroll
            for (int i = 0; i < 8; i++)
#pragma unroll
                for (int j = 0; j < 8; j++) acc[i][j] += a[i] * b[j];
        }
        __syncthreads();
    }
#pragma unroll
    for (int i = 0; i < 8; i++) {
        int gr = row0 + ty * 8 + i;
        if (gr >= NN) continue;
        float* o = out + (size_t)gr * 128 + tx * 8;
        float4 v0, v1;
        if (bias) {
            v0 = make_float4(acc[i][0] + bias[tx * 8 + 0], acc[i][1] + bias[tx * 8 + 1],
                             acc[i][2] + bias[tx * 8 + 2], acc[i][3] + bias[tx * 8 + 3]);
            v1 = make_float4(acc[i][4] + bias[tx * 8 + 4], acc[i][5] + bias[tx * 8 + 5],
                             acc[i][6] + bias[tx * 8 + 6], acc[i][7] + bias[tx * 8 + 7]);
        } else {
            v0 = make_float4(acc[i][0], acc[i][1], acc[i][2], acc[i][3]);
            v1 = make_float4(acc[i][4], acc[i][5], acc[i][6], acc[i][7]);
        }
        *(float4*)(o)     = v0;
        *(float4*)(o + 4) = v1;
    }
}

// ---------------- GCN aggregation (CSR gather, warp per node) ----------------
__global__ void k_gcn_csr() {
    int w = (blockIdx.x * blockDim.x + threadIdx.x) >> 5;
    int lane = threadIdx.x & 31;
    if (w >= NN) return;
    float dd = g_dinv[w];
    float4 v = ((const float4*)(g_xw + (size_t)w * 128))[lane];
    float sf = dd * dd;   // self-loop norm
    float4 acc = make_float4(v.x * sf, v.y * sf, v.z * sf, v.w * sf);
    int b = g_off[w], e = g_off[w + 1];
    for (int i = b; i < e; i++) {
        int s = g_csrc[i];
        float nr = g_dinv[s] * dd;
        float4 u = ((const float4*)(g_xw + (size_t)s * 128))[lane];
        acc.x += u.x * nr; acc.y += u.y * nr;
        acc.z += u.z * nr; acc.w += u.w * nr;
    }
    ((float4*)(g_acc + (size_t)w * 128))[lane] = acc;
}

// ---------------- fused GATv2 (CSR gather + online softmax, warp per node) ----
template <int H>
__global__ void k_gat_csr(const float* __restrict__ att) {
    int w = (blockIdx.x * blockDim.x + threadIdx.x) >> 5;
    int lane = threadIdx.x & 31;
    if (w >= NN) return;
    float4 r4 = ((const float4*)(g_xr + (size_t)w * 128))[lane];
    float4 a4 = ((const float4*)att)[lane];   // H*C == 128 in both layers

    // self edge first (weight exp(p-m)=1)
    float4 l4 = ((const float4*)(g_xl + (size_t)w * 128))[lane];
    float p = leaky(l4.x + r4.x) * a4.x + leaky(l4.y + r4.y) * a4.y +
              leaky(l4.z + r4.z) * a4.z + leaky(l4.w + r4.w) * a4.w;
    if (H == 8) {
        p += __shfl_xor_sync(0xffffffffu, p, 1);
        p += __shfl_xor_sync(0xffffffffu, p, 2);
    } else {
#pragma unroll
        for (int o = 16; o; o >>= 1) p += __shfl_xor_sync(0xffffffffu, p, o);
    }
    float m = p, den = 1.0f;
    float4 acc = l4;

    int b = g_off[w], e = g_off[w + 1];
    for (int i = b; i < e; i++) {
        int s = g_csrc[i];
        float4 v = ((const float4*)(g_xl + (size_t)s * 128))[lane];
        float q = leaky(v.x + r4.x) * a4.x + leaky(v.y + r4.y) * a4.y +
                  leaky(v.z + r4.z) * a4.z + leaky(v.w + r4.w) * a4.w;
        if (H == 8) {
            q += __shfl_xor_sync(0xffffffffu, q, 1);
            q += __shfl_xor_sync(0xffffffffu, q, 2);
        } else {
#pragma unroll
            for (int o = 16; o; o >>= 1) q += __shfl_xor_sync(0xffffffffu, q, o);
        }
        float nm = fmaxf(m, q);
        float so = __expf(m - nm);
        float wg = __expf(q - nm);
        den = den * so + wg;
        acc.x = acc.x * so + v.x * wg;
        acc.y = acc.y * so + v.y * wg;
        acc.z = acc.z * so + v.z * wg;
        acc.w = acc.w * so + v.w * wg;
        m = nm;
    }
    float inv = 1.0f / den;
    acc.x *= inv; acc.y *= inv; acc.z *= inv; acc.w *= inv;
    ((float4*)(g_acc + (size_t)w * 128))[lane] = acc;
}

// ---------------- graph LayerNorm ----------------
__global__ void k_ln_zero() { g_red[0] = 0.0; g_red[1] = 0.0; }

__global__ void k_ln_reduce(const float* __restrict__ in, const float* __restrict__ bias) {
    double s = 0.0, s2 = 0.0;
    for (int i = blockIdx.x * blockDim.x + threadIdx.x; i < ND; i += gridDim.x * blockDim.x) {
        double v = (double)(in[i] + bias[i & 127]);
        s += v; s2 += v * v;
    }
#pragma unroll
    for (int o = 16; o; o >>= 1) {
        s  += __shfl_down_sync(0xffffffffu, s, o);
        s2 += __shfl_down_sync(0xffffffffu, s2, o);
    }
    __shared__ double sh0[8], sh1[8];
    int w = threadIdx.x >> 5, l = threadIdx.x & 31;
    if (!l) { sh0[w] = s; sh1[w] = s2; }
    __syncthreads();
    if (threadIdx.x == 0) {
        double ts = 0.0, t2 = 0.0;
        int nw = blockDim.x >> 5;
        for (int i = 0; i < nw; i++) { ts += sh0[i]; t2 += sh1[i]; }
        atomicAdd(&g_red[0], ts);
        atomicAdd(&g_red[1], t2);
    }
}

template <bool RELU>
__global__ void k_ln_apply(const float* __restrict__ in, const float* __restrict__ bias,
                           const float* __restrict__ gm, const float* __restrict__ bt,
                           float* __restrict__ out) {
    int i = blockIdx.x * blockDim.x + threadIdx.x;
    if (i >= ND) return;
    double mu = g_red[0] * (1.0 / (double)ND);
    double var = g_red[1] * (1.0 / (double)ND) - mu * mu;
    float inv = 1.0f / (sqrtf(fmaxf((float)var, 0.0f)) + EPSF);
    int c = i & 127;
    float v = in[i] + bias[c];
    float r = (v - (float)mu) * inv * gm[c] + bt[c];
    if (RELU) r = fmaxf(r, 0.0f);
    out[i] = r;
}

// ---------------- launch ----------------
static inline int gridFor(long long n, int blk) { return (int)((n + blk - 1) / blk); }

extern "C" void kernel_launch(void* const* d_in, const int* in_sizes, int n_in,
                              void* d_out, int out_size) {
    const float* x   = (const float*)d_in[0];
    const int*   ei  = (const int*)d_in[1];
    const float* W0  = (const float*)d_in[2];
    const float* b0  = (const float*)d_in[3];
    const float* g0  = (const float*)d_in[4];
    const float* be0 = (const float*)d_in[5];
    const float* Wl1 = (const float*)d_in[6];
    const float* bl1 = (const float*)d_in[7];
    const float* Wr1 = (const float*)d_in[8];
    const float* br1 = (const float*)d_in[9];
    const float* att1= (const float*)d_in[10];
    const float* bg1 = (const float*)d_in[11];
    const float* g1  = (const float*)d_in[12];
    const float* be1 = (const float*)d_in[13];
    const float* W2  = (const float*)d_in[14];
    const float* b2  = (const float*)d_in[15];
    const float* g2  = (const float*)d_in[16];
    const float* be2 = (const float*)d_in[17];
    const float* Wl3 = (const float*)d_in[18];
    const float* bl3 = (const float*)d_in[19];
    const float* Wr3 = (const float*)d_in[20];
    const float* br3 = (const float*)d_in[21];
    const float* att3= (const float*)d_in[22];
    const float* bg3 = (const float*)d_in[23];
    const float* g3  = (const float*)d_in[24];
    const float* be3 = (const float*)d_in[25];
    float* out = (float*)d_out;

    const int* src = ei;
    const int* dst = ei + NE;

    const int BLK = 256;
    const int gN   = gridFor(NN, BLK);
    const int gE   = gridFor(NE, BLK);
    const int gND  = gridFor(ND, BLK);
    const int gNW  = gridFor((long long)NN * 32, BLK);  // warp-per-node
    const int gGemm = gridFor(NN, 128);

    float* p_h;   cudaGetSymbolAddress((void**)&p_h, g_h);
    float* p_xw;  cudaGetSymbolAddress((void**)&p_xw, g_xw);
    float* p_xl;  cudaGetSymbolAddress((void**)&p_xl, g_xl);
    float* p_xr;  cudaGetSymbolAddress((void**)&p_xr, g_xr);
    float* p_acc; cudaGetSymbolAddress((void**)&p_acc, g_acc);

    // ---- CSR build + degrees ----
    k_hist_zero<<<gN, BLK>>>();
    k_hist<<<gE, BLK>>>(dst);
    k_scan<<<1, 1024>>>();
    k_scatter<<<gE, BLK>>>(src, dst);

    // ---- layer 0: GCN + LN + ReLU ----
    gemm128<<<gGemm, BLK>>>(x, W0, nullptr, p_xw);
    k_gcn_csr<<<gNW, BLK>>>();
    k_ln_zero<<<1, 1>>>();
    k_ln_reduce<<<1024, BLK>>>(p_acc, b0);
    k_ln_apply<true><<<gND, BLK>>>(p_acc, b0, g0, be0, p_h);

    // ---- layer 1: GATv2 (H=8) + LN + ReLU ----
    gemm128<<<gGemm, BLK>>>(p_h, Wl1, bl1, p_xl);
    gemm128<<<gGemm, BLK>>>(p_h, Wr1, br1, p_xr);
    k_gat_csr<8><<<gNW, BLK>>>(att1);
    k_ln_zero<<<1, 1>>>();
    k_ln_reduce<<<1024, BLK>>>(p_acc, bg1);
    k_ln_apply<true><<<gND, BLK>>>(p_acc, bg1, g1, be1, p_h);

    // ---- layer 2: GCN + LN + ReLU ----
    gemm128<<<gGemm, BLK>>>(p_h, W2, nullptr, p_xw);
    k_gcn_csr<<<gNW, BLK>>>();
    k_ln_zero<<<1, 1>>>();
    k_ln_reduce<<<1024, BLK>>>(p_acc, b2);
    k_ln_apply<true><<<gND, BLK>>>(p_acc, b2, g2, be2, p_h);

    // ---- layer 3: GATv2 (H=1) + LN ----
    gemm128<<<gGemm, BLK>>>(p_h, Wl3, bl3, p_xl);
    gemm128<<<gGemm, BLK>>>(p_h, Wr3, br3, p_xr);
    k_gat_csr<1><<<gNW, BLK>>>(att3);
    k_ln_zero<<<1, 1>>>();
    k_ln_reduce<<<1024, BLK>>>(p_acc, bg3);
    k_ln_apply<false><<<gND, BLK>>>(p_acc, bg3, g3, be3, out);
}

// round 4
// speedup vs baseline: 2.9402x; 1.1715x over previous
#include <cuda_runtime.h>
#include <math.h>
#include <stdint.h>

#define NN 50000
#define NE 800000
#define DD 128
#define ND (NN * DD)
#define EPSF 1e-5f
#define NEGS 0.2f

// ---------------- scratch (static device globals; no allocation) ----------------
__device__ float g_h[ND];       // current node features
__device__ float g_xw[ND];      // GCN x@W
__device__ float g_xl[ND];      // GAT left transform
__device__ float g_xr[ND];      // GAT right transform
__device__ float g_acc[ND];     // aggregation output (bias already added)
__device__ float g_dinv[NN];    // deg^{-1/2}
__device__ int   g_cnt[NN];     // in-degree histogram (no self loop)
__device__ int   g_off[NN + 1]; // CSR offsets
__device__ int   g_cur[NN];     // scatter cursors
__device__ int   g_csrc[NE];    // CSR: src node per incoming edge
__device__ int   g_bsum[64];    // scan block totals
__device__ int   g_boff[64];    // scan block offsets
__device__ double g_red[8];     // (sum,sumsq) x 4 LN slots

__device__ __forceinline__ float leaky(float v) {
    return v > 0.0f ? v : NEGS * v;
}

// ---------------- CSR build ----------------
__global__ void k_hist_zero() {
    int i = blockIdx.x * blockDim.x + threadIdx.x;
    if (i < NN) g_cnt[i] = 0;
    if (i < 8) g_red[i] = 0.0;
}
__global__ void k_hist(const int* __restrict__ dst) {
    int e = blockIdx.x * blockDim.x + threadIdx.x;
    if (e < NE) atomicAdd(&g_cnt[dst[e]], 1);
}
// stage 1: per-block (1024-wide) exclusive scan; also deg^{-1/2}
__global__ void k_scan1() {
    __shared__ int warp_sums[32];
    int tid = threadIdx.x;
    int lane = tid & 31, wid = tid >> 5;
    int i = blockIdx.x * 1024 + tid;
    int v = (i < NN) ? g_cnt[i] : 0;
    int x = v;
#pragma unroll
    for (int o = 1; o < 32; o <<= 1) {
        int y = __shfl_up_sync(0xffffffffu, x, o);
        if (lane >= o) x += y;
    }
    if (lane == 31) warp_sums[wid] = x;
    __syncthreads();
    if (wid == 0) {
        int ws = warp_sums[lane];
#pragma unroll
        for (int o = 1; o < 32; o <<= 1) {
            int y = __shfl_up_sync(0xffffffffu, ws, o);
            if (lane >= o) ws += y;
        }
        warp_sums[lane] = ws;
    }
    __syncthreads();
    int incl = x + (wid ? warp_sums[wid - 1] : 0);
    if (i < NN) {
        g_off[i] = incl - v;             // block-local exclusive
        g_dinv[i] = rsqrtf((float)v + 1.0f);
    }
    if (tid == 1023) g_bsum[blockIdx.x] = incl;
}
// stage 2: scan the (<=64) block totals
__global__ void k_scan2(int nblk) {
    int lane = threadIdx.x;
    int v = (lane < nblk) ? g_bsum[lane] : 0;
    int x = v;
#pragma unroll
    for (int o = 1; o < 64; o <<= 1) {
        int y = __shfl_up_sync(0xffffffffu, x, o & 31);
        if ((lane & 31) >= (o & 31) && o < 32) x += y;
    }
    // simple serial scan instead (nblk<=64, trivial cost)
    if (lane == 0) {
        int run = 0;
        for (int k = 0; k < nblk; k++) { int t = g_bsum[k]; g_boff[k] = run; run += t; }
        g_off[NN] = NE;
    }
}
// stage 3: add block offsets, init cursors
__global__ void k_scan3() {
    int i = blockIdx.x * blockDim.x + threadIdx.x;
    if (i >= NN) return;
    int o = g_off[i] + g_boff[i >> 10];
    g_off[i] = o;
    g_cur[i] = o;
}
__global__ void k_scatter(const int* __restrict__ src, const int* __restrict__ dst) {
    int e = blockIdx.x * blockDim.x + threadIdx.x;
    if (e >= NE) return;
    int pos = atomicAdd(&g_cur[dst[e]], 1);
    g_csrc[pos] = src[e];
}

// ---------------- GEMM: out[N,128] = A[N,128] @ W[128,128] (+bias) ----------------
__global__ void __launch_bounds__(256) gemm128(
        const float* __restrict__ A, const float* __restrict__ W,
        const float* __restrict__ bias, float* __restrict__ out) {
    __shared__ float As[32][136];
    __shared__ float Ws[32][128];
    int t = threadIdx.x;
    int tx = t & 15, ty = t >> 4;
    int row0 = blockIdx.x * 128;

    float acc[8][8];
#pragma unroll
    for (int i = 0; i < 8; i++)
#pragma unroll
        for (int j = 0; j < 8; j++) acc[i][j] = 0.0f;

    float4 ra[4], rw[4];
    // preload k-tile 0
#pragma unroll
    for (int j = 0; j < 4; j++) {
        int lin = (t + j * 256) * 4;
        int r = lin >> 5, k = lin & 31;
        int gr = row0 + r;
        ra[j] = (gr < NN) ? *(const float4*)(A + (size_t)gr * 128 + k)
                          : make_float4(0.f, 0.f, 0.f, 0.f);
        int k2 = lin >> 7, c = lin & 127;
        rw[j] = *(const float4*)(W + (size_t)k2 * 128 + c);
    }

    for (int kt = 0; kt < 4; kt++) {
        // store staged tile
#pragma unroll
        for (int j = 0; j < 4; j++) {
            int lin = (t + j * 256) * 4;
            int r = lin >> 5, k = lin & 31;
            As[k + 0][r] = ra[j].x; As[k + 1][r] = ra[j].y;
            As[k + 2][r] = ra[j].z; As[k + 3][r] = ra[j].w;
            int k2 = lin >> 7, c = lin & 127;
            *(float4*)&Ws[k2][c] = rw[j];
        }
        __syncthreads();
        // issue next tile's loads before compute (latency hidden by FFMA loop)
        if (kt < 3) {
            int k0 = (kt + 1) * 32;
#pragma unroll
            for (int j = 0; j < 4; j++) {
                int lin = (t + j * 256) * 4;
                int r = lin >> 5, k = lin & 31;
                int gr = row0 + r;
                ra[j] = (gr < NN) ? *(const float4*)(A + (size_t)gr * 128 + k0 + k)
                                  : make_float4(0.f, 0.f, 0.f, 0.f);
                int k2 = lin >> 7, c = lin & 127;
                rw[j] = *(const float4*)(W + (size_t)(k0 + k2) * 128 + c);
            }
        }
#pragma unroll
        for (int k = 0; k < 32; k++) {
            float a[8], b[8];
            *(float4*)(a)     = *(float4*)&As[k][ty * 8];
            *(float4*)(a + 4) = *(float4*)&As[k][ty * 8 + 4];
            *(float4*)(b)     = *(float4*)&Ws[k][tx * 8];
            *(float4*)(b + 4) = *(float4*)&Ws[k][tx * 8 + 4];
#pragma unroll
            for (int i = 0; i < 8; i++)
#pragma unroll
                for (int j = 0; j < 8; j++) acc[i][j] += a[i] * b[j];
        }
        __syncthreads();
    }
#pragma unroll
    for (int i = 0; i < 8; i++) {
        int gr = row0 + ty * 8 + i;
        if (gr >= NN) continue;
        float* o = out + (size_t)gr * 128 + tx * 8;
        float4 v0, v1;
        if (bias) {
            v0 = make_float4(acc[i][0] + bias[tx * 8 + 0], acc[i][1] + bias[tx * 8 + 1],
                             acc[i][2] + bias[tx * 8 + 2], acc[i][3] + bias[tx * 8 + 3]);
            v1 = make_float4(acc[i][4] + bias[tx * 8 + 4], acc[i][5] + bias[tx * 8 + 5],
                             acc[i][6] + bias[tx * 8 + 6], acc[i][7] + bias[tx * 8 + 7]);
        } else {
            v0 = make_float4(acc[i][0], acc[i][1], acc[i][2], acc[i][3]);
            v1 = make_float4(acc[i][4], acc[i][5], acc[i][6], acc[i][7]);
        }
        *(float4*)(o)     = v0;
        *(float4*)(o + 4) = v1;
    }
}

// ---------------- block epilogue: fused LN partial reduction ----------------
__device__ __forceinline__ void ln_block_reduce(float s, float s2, int slot) {
    // warp reduce
#pragma unroll
    for (int o = 16; o; o >>= 1) {
        s  += __shfl_xor_sync(0xffffffffu, s, o);
        s2 += __shfl_xor_sync(0xffffffffu, s2, o);
    }
    __shared__ float shs[8], shs2[8];
    int wid = threadIdx.x >> 5, lane = threadIdx.x & 31;
    if (lane == 0) { shs[wid] = s; shs2[wid] = s2; }
    __syncthreads();
    if (threadIdx.x == 0) {
        double ts = 0.0, t2 = 0.0;
        int nw = blockDim.x >> 5;
        for (int k = 0; k < nw; k++) { ts += (double)shs[k]; t2 += (double)shs2[k]; }
        atomicAdd(&g_red[2 * slot], ts);
        atomicAdd(&g_red[2 * slot + 1], t2);
    }
}

// ---------------- GCN aggregation (CSR gather, warp per node, chunk-4) ------
__global__ void __launch_bounds__(256) k_gcn_csr(const float* __restrict__ bias, int slot) {
    int w = (blockIdx.x * blockDim.x + threadIdx.x) >> 5;
    int lane = threadIdx.x & 31;
    float s = 0.f, s2 = 0.f;
    if (w < NN) {
        float dd = g_dinv[w];
        float4 v = ((const float4*)(g_xw + (size_t)w * 128))[lane];
        float sf = dd * dd;
        float4 acc = make_float4(v.x * sf, v.y * sf, v.z * sf, v.w * sf);
        int b = g_off[w], e = g_off[w + 1];
        int i = b;
        for (; i + 4 <= e; i += 4) {
            int s0 = g_csrc[i], s1 = g_csrc[i + 1], s2i = g_csrc[i + 2], s3 = g_csrc[i + 3];
            float4 u0 = ((const float4*)(g_xw + (size_t)s0 * 128))[lane];
            float4 u1 = ((const float4*)(g_xw + (size_t)s1 * 128))[lane];
            float4 u2 = ((const float4*)(g_xw + (size_t)s2i * 128))[lane];
            float4 u3 = ((const float4*)(g_xw + (size_t)s3 * 128))[lane];
            float n0 = g_dinv[s0] * dd, n1 = g_dinv[s1] * dd;
            float n2 = g_dinv[s2i] * dd, n3 = g_dinv[s3] * dd;
            acc.x += u0.x * n0 + u1.x * n1 + u2.x * n2 + u3.x * n3;
            acc.y += u0.y * n0 + u1.y * n1 + u2.y * n2 + u3.y * n3;
            acc.z += u0.z * n0 + u1.z * n1 + u2.z * n2 + u3.z * n3;
            acc.w += u0.w * n0 + u1.w * n1 + u2.w * n2 + u3.w * n3;
        }
        for (; i < e; i++) {
            int sn = g_csrc[i];
            float nr = g_dinv[sn] * dd;
            float4 u = ((const float4*)(g_xw + (size_t)sn * 128))[lane];
            acc.x += u.x * nr; acc.y += u.y * nr;
            acc.z += u.z * nr; acc.w += u.w * nr;
        }
        float4 b4 = ((const float4*)bias)[lane];
        acc.x += b4.x; acc.y += b4.y; acc.z += b4.z; acc.w += b4.w;
        ((float4*)(g_acc + (size_t)w * 128))[lane] = acc;
        s  = acc.x + acc.y + acc.z + acc.w;
        s2 = acc.x * acc.x + acc.y * acc.y + acc.z * acc.z + acc.w * acc.w;
    }
    ln_block_reduce(s, s2, slot);
}

// ---------------- fused GATv2 (CSR gather + online softmax, chunk-4) --------
template <int H>
__device__ __forceinline__ float head_score(float4 v, float4 r4, float4 a4) {
    float q = leaky(v.x + r4.x) * a4.x + leaky(v.y + r4.y) * a4.y +
              leaky(v.z + r4.z) * a4.z + leaky(v.w + r4.w) * a4.w;
    if (H == 8) {
        q += __shfl_xor_sync(0xffffffffu, q, 1);
        q += __shfl_xor_sync(0xffffffffu, q, 2);
    } else {
#pragma unroll
        for (int o = 16; o; o >>= 1) q += __shfl_xor_sync(0xffffffffu, q, o);
    }
    return q;
}

template <int H>
__global__ void __launch_bounds__(256) k_gat_csr(const float* __restrict__ att,
                                                 const float* __restrict__ bias, int slot) {
    int w = (blockIdx.x * blockDim.x + threadIdx.x) >> 5;
    int lane = threadIdx.x & 31;
    float ps = 0.f, ps2 = 0.f;
    if (w < NN) {
        float4 r4 = ((const float4*)(g_xr + (size_t)w * 128))[lane];
        float4 a4 = ((const float4*)att)[lane];   // H*C == 128 in both layers

        // self edge first (weight exp(p-m)=1)
        float4 l4 = ((const float4*)(g_xl + (size_t)w * 128))[lane];
        float m = head_score<H>(l4, r4, a4);
        float den = 1.0f;
        float4 acc = l4;

        int b = g_off[w], e = g_off[w + 1];
        int i = b;
        for (; i + 4 <= e; i += 4) {
            int s0 = g_csrc[i], s1 = g_csrc[i + 1], s2 = g_csrc[i + 2], s3 = g_csrc[i + 3];
            float4 u0 = ((const float4*)(g_xl + (size_t)s0 * 128))[lane];
            float4 u1 = ((const float4*)(g_xl + (size_t)s1 * 128))[lane];
            float4 u2 = ((const float4*)(g_xl + (size_t)s2 * 128))[lane];
            float4 u3 = ((const float4*)(g_xl + (size_t)s3 * 128))[lane];
            float q0 = head_score<H>(u0, r4, a4);
            float q1 = head_score<H>(u1, r4, a4);
            float q2 = head_score<H>(u2, r4, a4);
            float q3 = head_score<H>(u3, r4, a4);
            float nm = fmaxf(fmaxf(fmaxf(q0, q1), fmaxf(q2, q3)), m);
            float so = __expf(m - nm);
            float w0 = __expf(q0 - nm), w1 = __expf(q1 - nm);
            float w2 = __expf(q2 - nm), w3 = __expf(q3 - nm);
            den = den * so + w0 + w1 + w2 + w3;
            acc.x = acc.x * so + u0.x * w0 + u1.x * w1 + u2.x * w2 + u3.x * w3;
            acc.y = acc.y * so + u0.y * w0 + u1.y * w1 + u2.y * w2 + u3.y * w3;
            acc.z = acc.z * so + u0.z * w0 + u1.z * w1 + u2.z * w2 + u3.z * w3;
            acc.w = acc.w * so + u0.w * w0 + u1.w * w1 + u2.w * w2 + u3.w * w3;
            m = nm;
        }
        for (; i < e; i++) {
            int sn = g_csrc[i];
            float4 v = ((const float4*)(g_xl + (size_t)sn * 128))[lane];
            float q = head_score<H>(v, r4, a4);
            float nm = fmaxf(m, q);
            float so = __expf(m - nm);
            float wg = __expf(q - nm);
            den = den * so + wg;
            acc.x = acc.x * so + v.x * wg;
            acc.y = acc.y * so + v.y * wg;
            acc.z = acc.z * so + v.z * wg;
            acc.w = acc.w * so + v.w * wg;
            m = nm;
        }
        float inv = 1.0f / den;
        float4 b4 = ((const float4*)bias)[lane];
        acc.x = acc.x * inv + b4.x;
        acc.y = acc.y * inv + b4.y;
        acc.z = acc.z * inv + b4.z;
        acc.w = acc.w * inv + b4.w;
        ((float4*)(g_acc + (size_t)w * 128))[lane] = acc;
        ps  = acc.x + acc.y + acc.z + acc.w;
        ps2 = acc.x * acc.x + acc.y * acc.y + acc.z * acc.z + acc.w * acc.w;
    }
    ln_block_reduce(ps, ps2, slot);
}

// ---------------- LayerNorm apply (input already biased) ----------------
template <bool RELU>
__global__ void k_ln_apply(const float* __restrict__ in,
                           const float* __restrict__ gm, const float* __restrict__ bt,
                           float* __restrict__ out, int slot) {
    int i = blockIdx.x * blockDim.x + threadIdx.x;
    if (i >= ND) return;
    double mu = g_red[2 * slot] * (1.0 / (double)ND);
    double var = g_red[2 * slot + 1] * (1.0 / (double)ND) - mu * mu;
    float inv = 1.0f / (sqrtf(fmaxf((float)var, 0.0f)) + EPSF);
    int c = i & 127;
    float v = in[i];
    float r = (v - (float)mu) * inv * gm[c] + bt[c];
    if (RELU) r = fmaxf(r, 0.0f);
    out[i] = r;
}

// ---------------- launch ----------------
static inline int gridFor(long long n, int blk) { return (int)((n + blk - 1) / blk); }

extern "C" void kernel_launch(void* const* d_in, const int* in_sizes, int n_in,
                              void* d_out, int out_size) {
    const float* x   = (const float*)d_in[0];
    const int*   ei  = (const int*)d_in[1];
    const float* W0  = (const float*)d_in[2];
    const float* b0  = (const float*)d_in[3];
    const float* g0  = (const float*)d_in[4];
    const float* be0 = (const float*)d_in[5];
    const float* Wl1 = (const float*)d_in[6];
    const float* bl1 = (const float*)d_in[7];
    const float* Wr1 = (const float*)d_in[8];
    const float* br1 = (const float*)d_in[9];
    const float* att1= (const float*)d_in[10];
    const float* bg1 = (const float*)d_in[11];
    const float* g1  = (const float*)d_in[12];
    const float* be1 = (const float*)d_in[13];
    const float* W2  = (const float*)d_in[14];
    const float* b2  = (const float*)d_in[15];
    const float* g2  = (const float*)d_in[16];
    const float* be2 = (const float*)d_in[17];
    const float* Wl3 = (const float*)d_in[18];
    const float* bl3 = (const float*)d_in[19];
    const float* Wr3 = (const float*)d_in[20];
    const float* br3 = (const float*)d_in[21];
    const float* att3= (const float*)d_in[22];
    const float* bg3 = (const float*)d_in[23];
    const float* g3  = (const float*)d_in[24];
    const float* be3 = (const float*)d_in[25];
    float* out = (float*)d_out;

    const int* src = ei;
    const int* dst = ei + NE;

    const int BLK = 256;
    const int gN   = gridFor(NN, BLK);
    const int gE   = gridFor(NE, BLK);
    const int gND  = gridFor(ND, BLK);
    const int gNW  = gridFor((long long)NN * 32, BLK);  // warp-per-node
    const int gGemm = gridFor(NN, 128);
    const int nScanBlk = gridFor(NN, 1024);

    float* p_h;   cudaGetSymbolAddress((void**)&p_h, g_h);
    float* p_xw;  cudaGetSymbolAddress((void**)&p_xw, g_xw);
    float* p_xl;  cudaGetSymbolAddress((void**)&p_xl, g_xl);
    float* p_xr;  cudaGetSymbolAddress((void**)&p_xr, g_xr);
    float* p_acc; cudaGetSymbolAddress((void**)&p_acc, g_acc);

    // ---- CSR build + degrees + LN accumulator zero ----
    k_hist_zero<<<gN, BLK>>>();
    k_hist<<<gE, BLK>>>(dst);
    k_scan1<<<nScanBlk, 1024>>>();
    k_scan2<<<1, 64>>>(nScanBlk);
    k_scan3<<<gN, BLK>>>();
    k_scatter<<<gE, BLK>>>(src, dst);

    // ---- layer 0: GCN + LN + ReLU ----
    gemm128<<<gGemm, BLK>>>(x, W0, nullptr, p_xw);
    k_gcn_csr<<<gNW, BLK>>>(b0, 0);
    k_ln_apply<true><<<gND, BLK>>>(p_acc, g0, be0, p_h, 0);

    // ---- layer 1: GATv2 (H=8) + LN + ReLU ----
    gemm128<<<gGemm, BLK>>>(p_h, Wl1, bl1, p_xl);
    gemm128<<<gGemm, BLK>>>(p_h, Wr1, br1, p_xr);
    k_gat_csr<8><<<gNW, BLK>>>(att1, bg1, 1);
    k_ln_apply<true><<<gND, BLK>>>(p_acc, g1, be1, p_h, 1);

    // ---- layer 2: GCN + LN + ReLU ----
    gemm128<<<gGemm, BLK>>>(p_h, W2, nullptr, p_xw);
    k_gcn_csr<<<gNW, BLK>>>(b2, 2);
    k_ln_apply<true><<<gND, BLK>>>(p_acc, g2, be2, p_h, 2);

    // ---- layer 3: GATv2 (H=1) + LN ----
    gemm128<<<gGemm, BLK>>>(p_h, Wl3, bl3, p_xl);
    gemm128<<<gGemm, BLK>>>(p_h, Wr3, br3, p_xr);
    k_gat_csr<1><<<gNW, BLK>>>(att3, bg3, 3);
    k_ln_apply<false><<<gND, BLK>>>(p_acc, g3, be3, out, 3);
}

// round 5
// speedup vs baseline: 3.1806x; 1.0818x over previous
#include <cuda_runtime.h>
#include <math.h>
#include <stdint.h>

#define NN 50000
#define NE 800000
#define DD 128
#define ND (NN * DD)
#define EPSF 1e-5f
#define NEGS 0.2f

// ---------------- scratch (static device globals; no allocation) ----------------
__device__ float g_xw[ND];      // GCN x@W
__device__ float g_xl[ND];      // GAT left transform
__device__ float g_xr[ND];      // GAT right transform
__device__ float g_acc[ND];     // aggregation output (bias added, pre-LN)
__device__ float g_dinv[NN];    // deg^{-1/2}
__device__ int   g_cnt[NN];     // in-degree histogram (no self loop)
__device__ int   g_off[NN + 1]; // CSR offsets
__device__ int   g_cur[NN];     // scatter cursors
__device__ int   g_csrc[NE];    // CSR: src node per incoming edge
__device__ int   g_bsum[64];    // scan block totals
__device__ int   g_boff[64];    // scan block offsets
__device__ double g_red[8];     // (sum,sumsq) x 4 LN slots

__device__ __forceinline__ float leaky(float v) {
    return v > 0.0f ? v : NEGS * v;
}

// ---------------- CSR build ----------------
__global__ void k_hist_zero() {
    int i = blockIdx.x * blockDim.x + threadIdx.x;
    if (i < NN) g_cnt[i] = 0;
    if (i < 8) g_red[i] = 0.0;
}
__global__ void k_hist(const int* __restrict__ dst) {
    int e = blockIdx.x * blockDim.x + threadIdx.x;
    if (e < NE) atomicAdd(&g_cnt[dst[e]], 1);
}
// stage 1: per-block (1024-wide) exclusive scan; also deg^{-1/2}
__global__ void k_scan1() {
    __shared__ int warp_sums[32];
    int tid = threadIdx.x;
    int lane = tid & 31, wid = tid >> 5;
    int i = blockIdx.x * 1024 + tid;
    int v = (i < NN) ? g_cnt[i] : 0;
    int x = v;
#pragma unroll
    for (int o = 1; o < 32; o <<= 1) {
        int y = __shfl_up_sync(0xffffffffu, x, o);
        if (lane >= o) x += y;
    }
    if (lane == 31) warp_sums[wid] = x;
    __syncthreads();
    if (wid == 0) {
        int ws = warp_sums[lane];
#pragma unroll
        for (int o = 1; o < 32; o <<= 1) {
            int y = __shfl_up_sync(0xffffffffu, ws, o);
            if (lane >= o) ws += y;
        }
        warp_sums[lane] = ws;
    }
    __syncthreads();
    int incl = x + (wid ? warp_sums[wid - 1] : 0);
    if (i < NN) {
        g_off[i] = incl - v;             // block-local exclusive
        g_dinv[i] = rsqrtf((float)v + 1.0f);
    }
    if (tid == 1023) g_bsum[blockIdx.x] = incl;
}
// stage 2: scan the (<=64) block totals (tiny)
__global__ void k_scan2(int nblk) {
    if (threadIdx.x == 0) {
        int run = 0;
        for (int k = 0; k < nblk; k++) { int t = g_bsum[k]; g_boff[k] = run; run += t; }
        g_off[NN] = NE;
    }
}
// stage 3: add block offsets, init cursors
__global__ void k_scan3() {
    int i = blockIdx.x * blockDim.x + threadIdx.x;
    if (i >= NN) return;
    int o = g_off[i] + g_boff[i >> 10];
    g_off[i] = o;
    g_cur[i] = o;
}
__global__ void k_scatter(const int* __restrict__ src, const int* __restrict__ dst) {
    int e = blockIdx.x * blockDim.x + threadIdx.x;
    if (e >= NE) return;
    int pos = atomicAdd(&g_cur[dst[e]], 1);
    g_csrc[pos] = src[e];
}

// ---------------- GEMM with optional fused input-LayerNorm+ReLU ----------------
// out[N,128] = f(A)[N,128] @ W[128,128] (+bias),  f = identity or relu(LN(.))
// gridDim.y selects (Wa,ba,outa) vs (Wb,bb,outb) to pair GAT GEMMs in one launch.
template <bool LNIN>
__global__ void __launch_bounds__(256) gemm128(
        const float* __restrict__ A,
        const float* __restrict__ Wa, const float* __restrict__ ba, float* __restrict__ outa,
        const float* __restrict__ Wb, const float* __restrict__ bb, float* __restrict__ outb,
        int slot, const float* __restrict__ gm, const float* __restrict__ bt) {
    __shared__ float As[32][136];
    __shared__ float Ws[32][128];
    const float* W    = blockIdx.y ? Wb : Wa;
    const float* bias = blockIdx.y ? bb : ba;
    float* out        = blockIdx.y ? outb : outa;

    int t = threadIdx.x;
    int tx = t & 15, ty = t >> 4;
    int row0 = blockIdx.x * 128;

    float fmu = 0.f, finv = 0.f;
    if (LNIN) {
        double mu = g_red[2 * slot] * (1.0 / (double)ND);
        double var = g_red[2 * slot + 1] * (1.0 / (double)ND) - mu * mu;
        fmu = (float)mu;
        finv = 1.0f / (sqrtf(fmaxf((float)var, 0.0f)) + EPSF);
    }

    float acc[8][8];
#pragma unroll
    for (int i = 0; i < 8; i++)
#pragma unroll
        for (int j = 0; j < 8; j++) acc[i][j] = 0.0f;

    float4 ra[4], rw[4];
    // preload k-tile 0
#pragma unroll
    for (int j = 0; j < 4; j++) {
        int lin = (t + j * 256) * 4;
        int r = lin >> 5, k = lin & 31;
        int gr = row0 + r;
        ra[j] = (gr < NN) ? *(const float4*)(A + (size_t)gr * 128 + k)
                          : make_float4(0.f, 0.f, 0.f, 0.f);
        int k2 = lin >> 7, c = lin & 127;
        rw[j] = *(const float4*)(W + (size_t)k2 * 128 + c);
    }

    for (int kt = 0; kt < 4; kt++) {
        // store staged tile (apply LN+ReLU transform on A elements here)
#pragma unroll
        for (int j = 0; j < 4; j++) {
            int lin = (t + j * 256) * 4;
            int r = lin >> 5, k = lin & 31;
            float4 v = ra[j];
            if (LNIN) {
                int c = kt * 32 + k;
                float4 gv = *(const float4*)(gm + c);
                float4 bv = *(const float4*)(bt + c);
                v.x = fmaxf((v.x - fmu) * finv * gv.x + bv.x, 0.f);
                v.y = fmaxf((v.y - fmu) * finv * gv.y + bv.y, 0.f);
                v.z = fmaxf((v.z - fmu) * finv * gv.z + bv.z, 0.f);
                v.w = fmaxf((v.w - fmu) * finv * gv.w + bv.w, 0.f);
            }
            As[k + 0][r] = v.x; As[k + 1][r] = v.y;
            As[k + 2][r] = v.z; As[k + 3][r] = v.w;
            int k2 = lin >> 7, c2 = lin & 127;
            *(float4*)&Ws[k2][c2] = rw[j];
        }
        __syncthreads();
        // issue next tile's loads before compute (latency hidden by FFMA loop)
        if (kt < 3) {
            int k0 = (kt + 1) * 32;
#pragma unroll
            for (int j = 0; j < 4; j++) {
                int lin = (t + j * 256) * 4;
                int r = lin >> 5, k = lin & 31;
                int gr = row0 + r;
                ra[j] = (gr < NN) ? *(const float4*)(A + (size_t)gr * 128 + k0 + k)
                                  : make_float4(0.f, 0.f, 0.f, 0.f);
                int k2 = lin >> 7, c = lin & 127;
                rw[j] = *(const float4*)(W + (size_t)(k0 + k2) * 128 + c);
            }
        }
#pragma unroll
        for (int k = 0; k < 32; k++) {
            float a[8], b[8];
            *(float4*)(a)     = *(float4*)&As[k][ty * 8];
            *(float4*)(a + 4) = *(float4*)&As[k][ty * 8 + 4];
            *(float4*)(b)     = *(float4*)&Ws[k][tx * 8];
            *(float4*)(b + 4) = *(float4*)&Ws[k][tx * 8 + 4];
#pragma unroll
            for (int i = 0; i < 8; i++)
#pragma unroll
                for (int j = 0; j < 8; j++) acc[i][j] += a[i] * b[j];
        }
        __syncthreads();
    }
#pragma unroll
    for (int i = 0; i < 8; i++) {
        int gr = row0 + ty * 8 + i;
        if (gr >= NN) continue;
        float* o = out + (size_t)gr * 128 + tx * 8;
        float4 v0, v1;
        if (bias) {
            v0 = make_float4(acc[i][0] + bias[tx * 8 + 0], acc[i][1] + bias[tx * 8 + 1],
                             acc[i][2] + bias[tx * 8 + 2], acc[i][3] + bias[tx * 8 + 3]);
            v1 = make_float4(acc[i][4] + bias[tx * 8 + 4], acc[i][5] + bias[tx * 8 + 5],
                             acc[i][6] + bias[tx * 8 + 6], acc[i][7] + bias[tx * 8 + 7]);
        } else {
            v0 = make_float4(acc[i][0], acc[i][1], acc[i][2], acc[i][3]);
            v1 = make_float4(acc[i][4], acc[i][5], acc[i][6], acc[i][7]);
        }
        *(float4*)(o)     = v0;
        *(float4*)(o + 4) = v1;
    }
}

// ---------------- block epilogue: fused LN partial reduction ----------------
__device__ __forceinline__ void ln_block_reduce(float s, float s2, int slot) {
#pragma unroll
    for (int o = 16; o; o >>= 1) {
        s  += __shfl_xor_sync(0xffffffffu, s, o);
        s2 += __shfl_xor_sync(0xffffffffu, s2, o);
    }
    __shared__ float shs[8], shs2[8];
    int wid = threadIdx.x >> 5, lane = threadIdx.x & 31;
    if (lane == 0) { shs[wid] = s; shs2[wid] = s2; }
    __syncthreads();
    if (threadIdx.x == 0) {
        double ts = 0.0, t2 = 0.0;
        int nw = blockDim.x >> 5;
        for (int k = 0; k < nw; k++) { ts += (double)shs[k]; t2 += (double)shs2[k]; }
        atomicAdd(&g_red[2 * slot], ts);
        atomicAdd(&g_red[2 * slot + 1], t2);
    }
}

// ---------------- GCN aggregation (CSR gather, warp per node, chunk-8) ------
__global__ void __launch_bounds__(256) k_gcn_csr(const float* __restrict__ bias, int slot) {
    int w = (blockIdx.x * blockDim.x + threadIdx.x) >> 5;
    int lane = threadIdx.x & 31;
    float s = 0.f, s2 = 0.f;
    if (w < NN) {
        float dd = g_dinv[w];
        float4 v = ((const float4*)(g_xw + (size_t)w * 128))[lane];
        float sf = dd * dd;
        float4 acc = make_float4(v.x * sf, v.y * sf, v.z * sf, v.w * sf);
        int b = g_off[w], e = g_off[w + 1];
        int i = b;
        for (; i + 8 <= e; i += 8) {
            int si[8];
#pragma unroll
            for (int j = 0; j < 8; j++) si[j] = g_csrc[i + j];
            float4 u[8];
#pragma unroll
            for (int j = 0; j < 8; j++)
                u[j] = ((const float4*)(g_xw + (size_t)si[j] * 128))[lane];
#pragma unroll
            for (int j = 0; j < 8; j++) {
                float nr = g_dinv[si[j]] * dd;
                acc.x += u[j].x * nr; acc.y += u[j].y * nr;
                acc.z += u[j].z * nr; acc.w += u[j].w * nr;
            }
        }
        for (; i < e; i++) {
            int sn = g_csrc[i];
            float nr = g_dinv[sn] * dd;
            float4 u = ((const float4*)(g_xw + (size_t)sn * 128))[lane];
            acc.x += u.x * nr; acc.y += u.y * nr;
            acc.z += u.z * nr; acc.w += u.w * nr;
        }
        float4 b4 = ((const float4*)bias)[lane];
        acc.x += b4.x; acc.y += b4.y; acc.z += b4.z; acc.w += b4.w;
        ((float4*)(g_acc + (size_t)w * 128))[lane] = acc;
        s  = acc.x + acc.y + acc.z + acc.w;
        s2 = acc.x * acc.x + acc.y * acc.y + acc.z * acc.z + acc.w * acc.w;
    }
    ln_block_reduce(s, s2, slot);
}

// ---------------- fused GATv2 (CSR gather + online softmax, chunk-4) --------
template <int H>
__device__ __forceinline__ float head_score(float4 v, float4 r4, float4 a4) {
    float q = leaky(v.x + r4.x) * a4.x + leaky(v.y + r4.y) * a4.y +
              leaky(v.z + r4.z) * a4.z + leaky(v.w + r4.w) * a4.w;
    if (H == 8) {
        q += __shfl_xor_sync(0xffffffffu, q, 1);
        q += __shfl_xor_sync(0xffffffffu, q, 2);
    } else {
#pragma unroll
        for (int o = 16; o; o >>= 1) q += __shfl_xor_sync(0xffffffffu, q, o);
    }
    return q;
}

template <int H>
__global__ void __launch_bounds__(256) k_gat_csr(const float* __restrict__ att,
                                                 const float* __restrict__ bias, int slot) {
    int w = (blockIdx.x * blockDim.x + threadIdx.x) >> 5;
    int lane = threadIdx.x & 31;
    float ps = 0.f, ps2 = 0.f;
    if (w < NN) {
        float4 r4 = ((const float4*)(g_xr + (size_t)w * 128))[lane];
        float4 a4 = ((const float4*)att)[lane];   // H*C == 128 in both layers

        // self edge first (weight exp(p-m)=1)
        float4 l4 = ((const float4*)(g_xl + (size_t)w * 128))[lane];
        float m = head_score<H>(l4, r4, a4);
        float den = 1.0f;
        float4 acc = l4;

        int b = g_off[w], e = g_off[w + 1];
        int i = b;
        for (; i + 4 <= e; i += 4) {
            int s0 = g_csrc[i], s1 = g_csrc[i + 1], s2 = g_csrc[i + 2], s3 = g_csrc[i + 3];
            float4 u0 = ((const float4*)(g_xl + (size_t)s0 * 128))[lane];
            float4 u1 = ((const float4*)(g_xl + (size_t)s1 * 128))[lane];
            float4 u2 = ((const float4*)(g_xl + (size_t)s2 * 128))[lane];
            float4 u3 = ((const float4*)(g_xl + (size_t)s3 * 128))[lane];
            float q0 = head_score<H>(u0, r4, a4);
            float q1 = head_score<H>(u1, r4, a4);
            float q2 = head_score<H>(u2, r4, a4);
            float q3 = head_score<H>(u3, r4, a4);
            float nm = fmaxf(fmaxf(fmaxf(q0, q1), fmaxf(q2, q3)), m);
            float so = __expf(m - nm);
            float w0 = __expf(q0 - nm), w1 = __expf(q1 - nm);
            float w2 = __expf(q2 - nm), w3 = __expf(q3 - nm);
            den = den * so + w0 + w1 + w2 + w3;
            acc.x = acc.x * so + u0.x * w0 + u1.x * w1 + u2.x * w2 + u3.x * w3;
            acc.y = acc.y * so + u0.y * w0 + u1.y * w1 + u2.y * w2 + u3.y * w3;
            acc.z = acc.z * so + u0.z * w0 + u1.z * w1 + u2.z * w2 + u3.z * w3;
            acc.w = acc.w * so + u0.w * w0 + u1.w * w1 + u2.w * w2 + u3.w * w3;
            m = nm;
        }
        for (; i < e; i++) {
            int sn = g_csrc[i];
            float4 v = ((const float4*)(g_xl + (size_t)sn * 128))[lane];
            float q = head_score<H>(v, r4, a4);
            float nm = fmaxf(m, q);
            float so = __expf(m - nm);
            float wg = __expf(q - nm);
            den = den * so + wg;
            acc.x = acc.x * so + v.x * wg;
            acc.y = acc.y * so + v.y * wg;
            acc.z = acc.z * so + v.z * wg;
            acc.w = acc.w * so + v.w * wg;
            m = nm;
        }
        float inv = 1.0f / den;
        float4 b4 = ((const float4*)bias)[lane];
        acc.x = acc.x * inv + b4.x;
        acc.y = acc.y * inv + b4.y;
        acc.z = acc.z * inv + b4.z;
        acc.w = acc.w * inv + b4.w;
        ((float4*)(g_acc + (size_t)w * 128))[lane] = acc;
        ps  = acc.x + acc.y + acc.z + acc.w;
        ps2 = acc.x * acc.x + acc.y * acc.y + acc.z * acc.z + acc.w * acc.w;
    }
    ln_block_reduce(ps, ps2, slot);
}

// ---------------- LayerNorm apply (final layer only) ----------------
__global__ void k_ln_apply(const float* __restrict__ in,
                           const float* __restrict__ gm, const float* __restrict__ bt,
                           float* __restrict__ out, int slot) {
    int i = blockIdx.x * blockDim.x + threadIdx.x;
    if (i >= ND) return;
    double mu = g_red[2 * slot] * (1.0 / (double)ND);
    double var = g_red[2 * slot + 1] * (1.0 / (double)ND) - mu * mu;
    float inv = 1.0f / (sqrtf(fmaxf((float)var, 0.0f)) + EPSF);
    int c = i & 127;
    float v = in[i];
    out[i] = (v - (float)mu) * inv * gm[c] + bt[c];
}

// ---------------- launch ----------------
static inline int gridFor(long long n, int blk) { return (int)((n + blk - 1) / blk); }

extern "C" void kernel_launch(void* const* d_in, const int* in_sizes, int n_in,
                              void* d_out, int out_size) {
    const float* x   = (const float*)d_in[0];
    const int*   ei  = (const int*)d_in[1];
    const float* W0  = (const float*)d_in[2];
    const float* b0  = (const float*)d_in[3];
    const float* g0  = (const float*)d_in[4];
    const float* be0 = (const float*)d_in[5];
    const float* Wl1 = (const float*)d_in[6];
    const float* bl1 = (const float*)d_in[7];
    const float* Wr1 = (const float*)d_in[8];
    const float* br1 = (const float*)d_in[9];
    const float* att1= (const float*)d_in[10];
    const float* bg1 = (const float*)d_in[11];
    const float* g1  = (const float*)d_in[12];
    const float* be1 = (const float*)d_in[13];
    const float* W2  = (const float*)d_in[14];
    const float* b2  = (const float*)d_in[15];
    const float* g2  = (const float*)d_in[16];
    const float* be2 = (const float*)d_in[17];
    const float* Wl3 = (const float*)d_in[18];
    const float* bl3 = (const float*)d_in[19];
    const float* Wr3 = (const float*)d_in[20];
    const float* br3 = (const float*)d_in[21];
    const float* att3= (const float*)d_in[22];
    const float* bg3 = (const float*)d_in[23];
    const float* g3  = (const float*)d_in[24];
    const float* be3 = (const float*)d_in[25];
    float* out = (float*)d_out;

    const int* src = ei;
    const int* dst = ei + NE;

    const int BLK = 256;
    const int gN   = gridFor(NN, BLK);
    const int gE   = gridFor(NE, BLK);
    const int gND  = gridFor(ND, BLK);
    const int gNW  = gridFor((long long)NN * 32, BLK);  // warp-per-node
    const int nGemmX = gridFor(NN, 128);
    const dim3 gG1(nGemmX, 1), gG2(nGemmX, 2);
    const int nScanBlk = gridFor(NN, 1024);

    float* p_xw;  cudaGetSymbolAddress((void**)&p_xw, g_xw);
    float* p_xl;  cudaGetSymbolAddress((void**)&p_xl, g_xl);
    float* p_xr;  cudaGetSymbolAddress((void**)&p_xr, g_xr);
    float* p_acc; cudaGetSymbolAddress((void**)&p_acc, g_acc);

    // ---- layer-0 GEMM first (independent of CSR build) ----
    gemm128<false><<<gG1, BLK>>>(x, W0, nullptr, p_xw,
                                 nullptr, nullptr, nullptr, 0, nullptr, nullptr);

    // ---- CSR build + degrees + LN accumulator zero ----
    k_hist_zero<<<gN, BLK>>>();
    k_hist<<<gE, BLK>>>(dst);
    k_scan1<<<nScanBlk, 1024>>>();
    k_scan2<<<1, 32>>>(nScanBlk);
    k_scan3<<<gN, BLK>>>();
    k_scatter<<<gE, BLK>>>(src, dst);

    // ---- layer 0: GCN agg (bias fused, LN stats in slot 0) ----
    k_gcn_csr<<<gNW, BLK>>>(b0, 0);

    // ---- layer 1: GATv2 (H=8); both GEMMs in one launch, LN0+ReLU fused ----
    gemm128<true><<<gG2, BLK>>>(p_acc, Wl1, bl1, p_xl,
                                Wr1, br1, p_xr, 0, g0, be0);
    k_gat_csr<8><<<gNW, BLK>>>(att1, bg1, 1);

    // ---- layer 2: GCN; GEMM with LN1+ReLU fused ----
    gemm128<true><<<gG1, BLK>>>(p_acc, W2, nullptr, p_xw,
                                nullptr, nullptr, nullptr, 1, g1, be1);
    k_gcn_csr<<<gNW, BLK>>>(b2, 2);

    // ---- layer 3: GATv2 (H=1); both GEMMs in one launch, LN2+ReLU fused ----
    gemm128<true><<<gG2, BLK>>>(p_acc, Wl3, bl3, p_xl,
                                Wr3, br3, p_xr, 2, g2, be2);
    k_gat_csr<1><<<gNW, BLK>>>(att3, bg3, 3);

    // ---- final LN -> output ----
    k_ln_apply<<<gND, BLK>>>(p_acc, g3, be3, out, 3);
}

// round 6
// speedup vs baseline: 3.1938x; 1.0041x over previous
#include <cuda_runtime.h>
#include <cuda_fp16.h>
#include <math.h>
#include <stdint.h>

#define NN 50000
#define NE 800000
#define DD 128
#define ND (NN * DD)
#define EPSF 1e-5f
#define NEGS 0.2f

// ---------------- scratch (static device globals; no allocation) ----------------
__device__ __half g_xwh[ND];    // GCN transform (half, gather payload)
__device__ __half g_xlh[ND];    // GAT left transform (half, gather payload)
__device__ float g_xr[ND];      // GAT right transform (fp32, read once per node)
__device__ float g_acc[ND];     // aggregation output (bias added, pre-LN, fp32)
__device__ float g_dinv[NN];    // deg^{-1/2}
__device__ int   g_cnt[NN];     // in-degree histogram (no self loop)
__device__ int   g_off[NN + 1]; // CSR offsets
__device__ int   g_cur[NN];     // scatter cursors
__device__ int   g_csrc[NE];    // CSR: src node per incoming edge
__device__ int   g_bsum[64];    // scan block totals
__device__ int   g_boff[64];    // scan block offsets
__device__ double g_red[8];     // (sum,sumsq) x 4 LN slots

__device__ __forceinline__ float leaky(float v) {
    return v > 0.0f ? v : NEGS * v;
}

// ---------------- CSR build ----------------
__global__ void k_hist_zero() {
    int i = blockIdx.x * blockDim.x + threadIdx.x;
    if (i < NN) g_cnt[i] = 0;
    if (i < 8) g_red[i] = 0.0;
}
__global__ void k_hist(const int* __restrict__ dst) {
    int e = blockIdx.x * blockDim.x + threadIdx.x;
    if (e < NE) atomicAdd(&g_cnt[dst[e]], 1);
}
// stage 1: per-block (1024-wide) exclusive scan; also deg^{-1/2}
__global__ void k_scan1() {
    __shared__ int warp_sums[32];
    int tid = threadIdx.x;
    int lane = tid & 31, wid = tid >> 5;
    int i = blockIdx.x * 1024 + tid;
    int v = (i < NN) ? g_cnt[i] : 0;
    int x = v;
#pragma unroll
    for (int o = 1; o < 32; o <<= 1) {
        int y = __shfl_up_sync(0xffffffffu, x, o);
        if (lane >= o) x += y;
    }
    if (lane == 31) warp_sums[wid] = x;
    __syncthreads();
    if (wid == 0) {
        int ws = warp_sums[lane];
#pragma unroll
        for (int o = 1; o < 32; o <<= 1) {
            int y = __shfl_up_sync(0xffffffffu, ws, o);
            if (lane >= o) ws += y;
        }
        warp_sums[lane] = ws;
    }
    __syncthreads();
    int incl = x + (wid ? warp_sums[wid - 1] : 0);
    if (i < NN) {
        g_off[i] = incl - v;             // block-local exclusive
        g_dinv[i] = rsqrtf((float)v + 1.0f);
    }
    if (tid == 1023) g_bsum[blockIdx.x] = incl;
}
// stage 2: parallel exclusive scan of <=64 block totals (2 warps + shared)
__global__ void k_scan2(int nblk) {
    __shared__ int w0sum;
    int tid = threadIdx.x;           // 64 threads
    int lane = tid & 31, wid = tid >> 5;
    int v = (tid < nblk) ? g_bsum[tid] : 0;
    int x = v;
#pragma unroll
    for (int o = 1; o < 32; o <<= 1) {
        int y = __shfl_up_sync(0xffffffffu, x, o);
        if (lane >= o) x += y;
    }
    if (tid == 31) w0sum = x;
    __syncthreads();
    int excl = x - v + (wid ? w0sum : 0);
    if (tid < nblk) g_boff[tid] = excl;
    if (tid == 0) g_off[NN] = NE;
}
// stage 3: add block offsets, init cursors
__global__ void k_scan3() {
    int i = blockIdx.x * blockDim.x + threadIdx.x;
    if (i >= NN) return;
    int o = g_off[i] + g_boff[i >> 10];
    g_off[i] = o;
    g_cur[i] = o;
}
__global__ void k_scatter(const int* __restrict__ src, const int* __restrict__ dst) {
    int e = blockIdx.x * blockDim.x + threadIdx.x;
    if (e >= NE) return;
    int pos = atomicAdd(&g_cur[dst[e]], 1);
    g_csrc[pos] = src[e];
}

// ---------------- GEMM with optional fused input-LayerNorm+ReLU ----------------
// out = f(A)[N,128] @ W[128,128] (+bias);  f = identity or relu(LN(.))
// PAIR: gridDim.y=2; y=0 writes HALF to houta (Wa,ba), y=1 writes FLOAT to foutb (Wb,bb).
// !PAIR: single HALF output houta.
template <bool LNIN, bool PAIR>
__global__ void __launch_bounds__(256) gemm128(
        const float* __restrict__ A,
        const float* __restrict__ Wa, const float* __restrict__ ba, __half* __restrict__ houta,
        const float* __restrict__ Wb, const float* __restrict__ bb, float* __restrict__ foutb,
        int slot, const float* __restrict__ gm, const float* __restrict__ bt) {
    __shared__ float As[32][136];
    __shared__ float Ws[32][128];
    bool second = PAIR && (blockIdx.y != 0);
    const float* W    = second ? Wb : Wa;
    const float* bias = second ? bb : ba;

    int t = threadIdx.x;
    int tx = t & 15, ty = t >> 4;
    int row0 = blockIdx.x * 128;

    float fmu = 0.f, finv = 0.f;
    if (LNIN) {
        double mu = g_red[2 * slot] * (1.0 / (double)ND);
        double var = g_red[2 * slot + 1] * (1.0 / (double)ND) - mu * mu;
        fmu = (float)mu;
        finv = 1.0f / (sqrtf(fmaxf((float)var, 0.0f)) + EPSF);
    }

    float acc[8][8];
#pragma unroll
    for (int i = 0; i < 8; i++)
#pragma unroll
        for (int j = 0; j < 8; j++) acc[i][j] = 0.0f;

    float4 ra[4], rw[4];
#pragma unroll
    for (int j = 0; j < 4; j++) {
        int lin = (t + j * 256) * 4;
        int r = lin >> 5, k = lin & 31;
        int gr = row0 + r;
        ra[j] = (gr < NN) ? *(const float4*)(A + (size_t)gr * 128 + k)
                          : make_float4(0.f, 0.f, 0.f, 0.f);
        int k2 = lin >> 7, c = lin & 127;
        rw[j] = *(const float4*)(W + (size_t)k2 * 128 + c);
    }

    for (int kt = 0; kt < 4; kt++) {
#pragma unroll
        for (int j = 0; j < 4; j++) {
            int lin = (t + j * 256) * 4;
            int r = lin >> 5, k = lin & 31;
            float4 v = ra[j];
            if (LNIN) {
                int c = kt * 32 + k;
                float4 gv = *(const float4*)(gm + c);
                float4 bv = *(const float4*)(bt + c);
                v.x = fmaxf((v.x - fmu) * finv * gv.x + bv.x, 0.f);
                v.y = fmaxf((v.y - fmu) * finv * gv.y + bv.y, 0.f);
                v.z = fmaxf((v.z - fmu) * finv * gv.z + bv.z, 0.f);
                v.w = fmaxf((v.w - fmu) * finv * gv.w + bv.w, 0.f);
            }
            As[k + 0][r] = v.x; As[k + 1][r] = v.y;
            As[k + 2][r] = v.z; As[k + 3][r] = v.w;
            int k2 = lin >> 7, c2 = lin & 127;
            *(float4*)&Ws[k2][c2] = rw[j];
        }
        __syncthreads();
        if (kt < 3) {
            int k0 = (kt + 1) * 32;
#pragma unroll
            for (int j = 0; j < 4; j++) {
                int lin = (t + j * 256) * 4;
                int r = lin >> 5, k = lin & 31;
                int gr = row0 + r;
                ra[j] = (gr < NN) ? *(const float4*)(A + (size_t)gr * 128 + k0 + k)
                                  : make_float4(0.f, 0.f, 0.f, 0.f);
                int k2 = lin >> 7, c = lin & 127;
                rw[j] = *(const float4*)(W + (size_t)(k0 + k2) * 128 + c);
            }
        }
#pragma unroll
        for (int k = 0; k < 32; k++) {
            float a[8], b[8];
            *(float4*)(a)     = *(float4*)&As[k][ty * 8];
            *(float4*)(a + 4) = *(float4*)&As[k][ty * 8 + 4];
            *(float4*)(b)     = *(float4*)&Ws[k][tx * 8];
            *(float4*)(b + 4) = *(float4*)&Ws[k][tx * 8 + 4];
#pragma unroll
            for (int i = 0; i < 8; i++)
#pragma unroll
                for (int j = 0; j < 8; j++) acc[i][j] += a[i] * b[j];
        }
        __syncthreads();
    }
#pragma unroll
    for (int i = 0; i < 8; i++) {
        int gr = row0 + ty * 8 + i;
        if (gr >= NN) continue;
        float r[8];
#pragma unroll
        for (int j = 0; j < 8; j++)
            r[j] = bias ? acc[i][j] + bias[tx * 8 + j] : acc[i][j];
        if (second) {
            float* o = foutb + (size_t)gr * 128 + tx * 8;
            *(float4*)(o)     = make_float4(r[0], r[1], r[2], r[3]);
            *(float4*)(o + 4) = make_float4(r[4], r[5], r[6], r[7]);
        } else {
            __half2 hh[4];
            hh[0] = __floats2half2_rn(r[0], r[1]);
            hh[1] = __floats2half2_rn(r[2], r[3]);
            hh[2] = __floats2half2_rn(r[4], r[5]);
            hh[3] = __floats2half2_rn(r[6], r[7]);
            *(uint4*)(houta + (size_t)gr * 128 + tx * 8) = *(uint4*)hh;
        }
    }
}

// ---------------- block epilogue: fused LN partial reduction ----------------
__device__ __forceinline__ void ln_block_reduce(float s, float s2, int slot) {
#pragma unroll
    for (int o = 16; o; o >>= 1) {
        s  += __shfl_xor_sync(0xffffffffu, s, o);
        s2 += __shfl_xor_sync(0xffffffffu, s2, o);
    }
    __shared__ float shs[8], shs2[8];
    int wid = threadIdx.x >> 5, lane = threadIdx.x & 31;
    if (lane == 0) { shs[wid] = s; shs2[wid] = s2; }
    __syncthreads();
    if (threadIdx.x == 0) {
        double ts = 0.0, t2 = 0.0;
        int nw = blockDim.x >> 5;
        for (int k = 0; k < nw; k++) { ts += (double)shs[k]; t2 += (double)shs2[k]; }
        atomicAdd(&g_red[2 * slot], ts);
        atomicAdd(&g_red[2 * slot + 1], t2);
    }
}

// load 4 channels (lane's slice) of a half row, as two float2
__device__ __forceinline__ void load_h4(const __half* base, int node, int lane,
                                        float2& f0, float2& f1) {
    uint2 raw = *(const uint2*)(base + (size_t)node * 128 + lane * 4);
    f0 = __half22float2(*(__half2*)&raw.x);
    f1 = __half22float2(*(__half2*)&raw.y);
}

// ---------------- GCN aggregation (CSR gather, warp per node, chunk-8, fp16 src) ---
__global__ void __launch_bounds__(256) k_gcn_csr(const float* __restrict__ bias, int slot) {
    int w = (blockIdx.x * blockDim.x + threadIdx.x) >> 5;
    int lane = threadIdx.x & 31;
    float s = 0.f, s2 = 0.f;
    if (w < NN) {
        float dd = g_dinv[w];
        float2 v0, v1;
        load_h4(g_xwh, w, lane, v0, v1);
        float sf = dd * dd;
        float4 acc = make_float4(v0.x * sf, v0.y * sf, v1.x * sf, v1.y * sf);
        int b = g_off[w], e = g_off[w + 1];
        int i = b;
        for (; i + 8 <= e; i += 8) {
            int si[8];
#pragma unroll
            for (int j = 0; j < 8; j++) si[j] = g_csrc[i + j];
            uint2 raw[8];
#pragma unroll
            for (int j = 0; j < 8; j++)
                raw[j] = *(const uint2*)(g_xwh + (size_t)si[j] * 128 + lane * 4);
#pragma unroll
            for (int j = 0; j < 8; j++) {
                float nr = g_dinv[si[j]] * dd;
                float2 a = __half22float2(*(__half2*)&raw[j].x);
                float2 c = __half22float2(*(__half2*)&raw[j].y);
                acc.x += a.x * nr; acc.y += a.y * nr;
                acc.z += c.x * nr; acc.w += c.y * nr;
            }
        }
        for (; i < e; i++) {
            int sn = g_csrc[i];
            float nr = g_dinv[sn] * dd;
            float2 a0, a1;
            load_h4(g_xwh, sn, lane, a0, a1);
            acc.x += a0.x * nr; acc.y += a0.y * nr;
            acc.z += a1.x * nr; acc.w += a1.y * nr;
        }
        float4 b4 = ((const float4*)bias)[lane];
        acc.x += b4.x; acc.y += b4.y; acc.z += b4.z; acc.w += b4.w;
        ((float4*)(g_acc + (size_t)w * 128))[lane] = acc;
        s  = acc.x + acc.y + acc.z + acc.w;
        s2 = acc.x * acc.x + acc.y * acc.y + acc.z * acc.z + acc.w * acc.w;
    }
    ln_block_reduce(s, s2, slot);
}

// ---------------- fused GATv2 (CSR gather + online softmax, chunk-4, fp16 src) ----
template <int H>
__device__ __forceinline__ float head_score(float4 v, float4 r4, float4 a4) {
    float q = leaky(v.x + r4.x) * a4.x + leaky(v.y + r4.y) * a4.y +
              leaky(v.z + r4.z) * a4.z + leaky(v.w + r4.w) * a4.w;
    if (H == 8) {
        q += __shfl_xor_sync(0xffffffffu, q, 1);
        q += __shfl_xor_sync(0xffffffffu, q, 2);
    } else {
#pragma unroll
        for (int o = 16; o; o >>= 1) q += __shfl_xor_sync(0xffffffffu, q, o);
    }
    return q;
}

__device__ __forceinline__ float4 h4_to_f4(uint2 raw) {
    float2 a = __half22float2(*(__half2*)&raw.x);
    float2 b = __half22float2(*(__half2*)&raw.y);
    return make_float4(a.x, a.y, b.x, b.y);
}

template <int H>
__global__ void __launch_bounds__(256) k_gat_csr(const float* __restrict__ att,
                                                 const float* __restrict__ bias, int slot) {
    int w = (blockIdx.x * blockDim.x + threadIdx.x) >> 5;
    int lane = threadIdx.x & 31;
    float ps = 0.f, ps2 = 0.f;
    if (w < NN) {
        float4 r4 = ((const float4*)(g_xr + (size_t)w * 128))[lane];
        float4 a4 = ((const float4*)att)[lane];   // H*C == 128 in both layers

        // self edge first
        uint2 rawl = *(const uint2*)(g_xlh + (size_t)w * 128 + lane * 4);
        float4 l4 = h4_to_f4(rawl);
        float m = head_score<H>(l4, r4, a4);
        float den = 1.0f;
        float4 acc = l4;

        int b = g_off[w], e = g_off[w + 1];
        int i = b;
        for (; i + 4 <= e; i += 4) {
            int s0 = g_csrc[i], s1 = g_csrc[i + 1], s2 = g_csrc[i + 2], s3 = g_csrc[i + 3];
            uint2 w0r = *(const uint2*)(g_xlh + (size_t)s0 * 128 + lane * 4);
            uint2 w1r = *(const uint2*)(g_xlh + (size_t)s1 * 128 + lane * 4);
            uint2 w2r = *(const uint2*)(g_xlh + (size_t)s2 * 128 + lane * 4);
            uint2 w3r = *(const uint2*)(g_xlh + (size_t)s3 * 128 + lane * 4);
            float4 u0 = h4_to_f4(w0r), u1 = h4_to_f4(w1r);
            float4 u2 = h4_to_f4(w2r), u3 = h4_to_f4(w3r);
            float q0 = head_score<H>(u0, r4, a4);
            float q1 = head_score<H>(u1, r4, a4);
            float q2 = head_score<H>(u2, r4, a4);
            float q3 = head_score<H>(u3, r4, a4);
            float nm = fmaxf(fmaxf(fmaxf(q0, q1), fmaxf(q2, q3)), m);
            float so = __expf(m - nm);
            float w0 = __expf(q0 - nm), w1 = __expf(q1 - nm);
            float w2 = __expf(q2 - nm), w3 = __expf(q3 - nm);
            den = den * so + w0 + w1 + w2 + w3;
            acc.x = acc.x * so + u0.x * w0 + u1.x * w1 + u2.x * w2 + u3.x * w3;
            acc.y = acc.y * so + u0.y * w0 + u1.y * w1 + u2.y * w2 + u3.y * w3;
            acc.z = acc.z * so + u0.z * w0 + u1.z * w1 + u2.z * w2 + u3.z * w3;
            acc.w = acc.w * so + u0.w * w0 + u1.w * w1 + u2.w * w2 + u3.w * w3;
            m = nm;
        }
        for (; i < e; i++) {
            int sn = g_csrc[i];
            uint2 vr = *(const uint2*)(g_xlh + (size_t)sn * 128 + lane * 4);
            float4 v = h4_to_f4(vr);
            float q = head_score<H>(v, r4, a4);
            float nm = fmaxf(m, q);
            float so = __expf(m - nm);
            float wg = __expf(q - nm);
            den = den * so + wg;
            acc.x = acc.x * so + v.x * wg;
            acc.y = acc.y * so + v.y * wg;
            acc.z = acc.z * so + v.z * wg;
            acc.w = acc.w * so + v.w * wg;
            m = nm;
        }
        float inv = 1.0f / den;
        float4 b4 = ((const float4*)bias)[lane];
        acc.x = acc.x * inv + b4.x;
        acc.y = acc.y * inv + b4.y;
        acc.z = acc.z * inv + b4.z;
        acc.w = acc.w * inv + b4.w;
        ((float4*)(g_acc + (size_t)w * 128))[lane] = acc;
        ps  = acc.x + acc.y + acc.z + acc.w;
        ps2 = acc.x * acc.x + acc.y * acc.y + acc.z * acc.z + acc.w * acc.w;
    }
    ln_block_reduce(ps, ps2, slot);
}

// ---------------- LayerNorm apply (final layer only) ----------------
__global__ void k_ln_apply(const float* __restrict__ in,
                           const float* __restrict__ gm, const float* __restrict__ bt,
                           float* __restrict__ out, int slot) {
    int i = blockIdx.x * blockDim.x + threadIdx.x;
    if (i >= ND) return;
    double mu = g_red[2 * slot] * (1.0 / (double)ND);
    double var = g_red[2 * slot + 1] * (1.0 / (double)ND) - mu * mu;
    float inv = 1.0f / (sqrtf(fmaxf((float)var, 0.0f)) + EPSF);
    int c = i & 127;
    float v = in[i];
    out[i] = (v - (float)mu) * inv * gm[c] + bt[c];
}

// ---------------- launch ----------------
static inline int gridFor(long long n, int blk) { return (int)((n + blk - 1) / blk); }

extern "C" void kernel_launch(void* const* d_in, const int* in_sizes, int n_in,
                              void* d_out, int out_size) {
    const float* x   = (const float*)d_in[0];
    const int*   ei  = (const int*)d_in[1];
    const float* W0  = (const float*)d_in[2];
    const float* b0  = (const float*)d_in[3];
    const float* g0  = (const float*)d_in[4];
    const float* be0 = (const float*)d_in[5];
    const float* Wl1 = (const float*)d_in[6];
    const float* bl1 = (const float*)d_in[7];
    const float* Wr1 = (const float*)d_in[8];
    const float* br1 = (const float*)d_in[9];
    const float* att1= (const float*)d_in[10];
    const float* bg1 = (const float*)d_in[11];
    const float* g1  = (const float*)d_in[12];
    const float* be1 = (const float*)d_in[13];
    const float* W2  = (const float*)d_in[14];
    const float* b2  = (const float*)d_in[15];
    const float* g2  = (const float*)d_in[16];
    const float* be2 = (const float*)d_in[17];
    const float* Wl3 = (const float*)d_in[18];
    const float* bl3 = (const float*)d_in[19];
    const float* Wr3 = (const float*)d_in[20];
    const float* br3 = (const float*)d_in[21];
    const float* att3= (const float*)d_in[22];
    const float* bg3 = (const float*)d_in[23];
    const float* g3  = (const float*)d_in[24];
    const float* be3 = (const float*)d_in[25];
    float* out = (float*)d_out;

    const int* src = ei;
    const int* dst = ei + NE;

    const int BLK = 256;
    const int gN   = gridFor(NN, BLK);
    const int gE   = gridFor(NE, BLK);
    const int gND  = gridFor(ND, BLK);
    const int gNW  = gridFor((long long)NN * 32, BLK);  // warp-per-node
    const int nGemmX = gridFor(NN, 128);
    const dim3 gG1(nGemmX, 1), gG2(nGemmX, 2);
    const int nScanBlk = gridFor(NN, 1024);

    __half* p_xwh; cudaGetSymbolAddress((void**)&p_xwh, g_xwh);
    __half* p_xlh; cudaGetSymbolAddress((void**)&p_xlh, g_xlh);
    float* p_xr;  cudaGetSymbolAddress((void**)&p_xr, g_xr);
    float* p_acc; cudaGetSymbolAddress((void**)&p_acc, g_acc);

    // ---- layer-0 GEMM first (independent of CSR build) ----
    gemm128<false, false><<<gG1, BLK>>>(x, W0, nullptr, p_xwh,
                                        nullptr, nullptr, nullptr, 0, nullptr, nullptr);

    // ---- CSR build + degrees + LN accumulator zero ----
    k_hist_zero<<<gN, BLK>>>();
    k_hist<<<gE, BLK>>>(dst);
    k_scan1<<<nScanBlk, 1024>>>();
    k_scan2<<<1, 64>>>(nScanBlk);
    k_scan3<<<gN, BLK>>>();
    k_scatter<<<gE, BLK>>>(src, dst);

    // ---- layer 0: GCN agg (bias fused, LN stats in slot 0) ----
    k_gcn_csr<<<gNW, BLK>>>(b0, 0);

    // ---- layer 1: GATv2 (H=8); both GEMMs in one launch, LN0+ReLU fused ----
    gemm128<true, true><<<gG2, BLK>>>(p_acc, Wl1, bl1, p_xlh,
                                      Wr1, br1, p_xr, 0, g0, be0);
    k_gat_csr<8><<<gNW, BLK>>>(att1, bg1, 1);

    // ---- layer 2: GCN; GEMM with LN1+ReLU fused ----
    gemm128<true, false><<<gG1, BLK>>>(p_acc, W2, nullptr, p_xwh,
                                       nullptr, nullptr, nullptr, 1, g1, be1);
    k_gcn_csr<<<gNW, BLK>>>(b2, 2);

    // ---- layer 3: GATv2 (H=1); both GEMMs in one launch, LN2+ReLU fused ----
    gemm128<true, true><<<gG2, BLK>>>(p_acc, Wl3, bl3, p_xlh,
                                      Wr3, br3, p_xr, 2, g2, be2);
    k_gat_csr<1><<<gNW, BLK>>>(att3, bg3, 3);

    // ---- final LN -> output ----
    k_ln_apply<<<gND, BLK>>>(p_acc, g3, be3, out, 3);
}

// round 7
// speedup vs baseline: 3.7164x; 1.1636x over previous
#include <cuda_runtime.h>
#include <cuda_fp16.h>
#include <mma.h>
#include <math.h>
#include <stdint.h>

using namespace nvcuda;

#define NN 50000
#define NE 800000
#define DD 128
#define ND (NN * DD)
#define EPSF 1e-5f
#define NEGS 0.2f

// ---------------- scratch (static device globals; no allocation) ----------------
__device__ __half g_xwh[ND];    // GCN transform (half, gather payload)
__device__ __half g_xlh[ND];    // GAT left transform (half, gather payload)
__device__ float g_xr[ND];      // GAT right transform (fp32)
__device__ float g_acc[ND];     // aggregation output (bias added, pre-LN, fp32)
__device__ __half g_wh[6 * DD * DD];  // fp16 weight copies
__device__ float g_dinv[NN];    // deg^{-1/2}
__device__ int   g_cnt[NN];     // in-degree histogram (no self loop)
__device__ int   g_off[NN + 1]; // CSR offsets
__device__ int   g_cur[NN];     // scatter cursors
__device__ int   g_csrc[NE];    // CSR: src node per incoming edge
__device__ int   g_bsum[64];    // scan block totals
__device__ int   g_boff[64];    // scan block offsets
__device__ double g_red[8];     // (sum,sumsq) x 4 LN slots

__device__ __forceinline__ float leaky(float v) {
    return v > 0.0f ? v : NEGS * v;
}

// ---------------- weight conversion (fp32 -> fp16, all 6 matrices) ----------------
__global__ void k_cvt_w(const float* __restrict__ w0, const float* __restrict__ w1,
                        const float* __restrict__ w2, const float* __restrict__ w3,
                        const float* __restrict__ w4, const float* __restrict__ w5) {
    const float* ws[6] = {w0, w1, w2, w3, w4, w5};
    int m = blockIdx.y;
    int i = blockIdx.x * blockDim.x + threadIdx.x;
    if (i < DD * DD) g_wh[m * DD * DD + i] = __float2half_rn(ws[m][i]);
}

// ---------------- CSR build ----------------
__global__ void k_hist_zero() {
    int i = blockIdx.x * blockDim.x + threadIdx.x;
    if (i < NN) g_cnt[i] = 0;
    if (i < 8) g_red[i] = 0.0;
}
__global__ void k_hist(const int* __restrict__ dst) {
    int e = blockIdx.x * blockDim.x + threadIdx.x;
    if (e < NE) atomicAdd(&g_cnt[dst[e]], 1);
}
__global__ void k_scan1() {
    __shared__ int warp_sums[32];
    int tid = threadIdx.x;
    int lane = tid & 31, wid = tid >> 5;
    int i = blockIdx.x * 1024 + tid;
    int v = (i < NN) ? g_cnt[i] : 0;
    int x = v;
#pragma unroll
    for (int o = 1; o < 32; o <<= 1) {
        int y = __shfl_up_sync(0xffffffffu, x, o);
        if (lane >= o) x += y;
    }
    if (lane == 31) warp_sums[wid] = x;
    __syncthreads();
    if (wid == 0) {
        int ws = warp_sums[lane];
#pragma unroll
        for (int o = 1; o < 32; o <<= 1) {
            int y = __shfl_up_sync(0xffffffffu, ws, o);
            if (lane >= o) ws += y;
        }
        warp_sums[lane] = ws;
    }
    __syncthreads();
    int incl = x + (wid ? warp_sums[wid - 1] : 0);
    if (i < NN) {
        g_off[i] = incl - v;
        g_dinv[i] = rsqrtf((float)v + 1.0f);
    }
    if (tid == 1023) g_bsum[blockIdx.x] = incl;
}
__global__ void k_scan2(int nblk) {
    __shared__ int w0sum;
    int tid = threadIdx.x;
    int lane = tid & 31, wid = tid >> 5;
    int v = (tid < nblk) ? g_bsum[tid] : 0;
    int x = v;
#pragma unroll
    for (int o = 1; o < 32; o <<= 1) {
        int y = __shfl_up_sync(0xffffffffu, x, o);
        if (lane >= o) x += y;
    }
    if (tid == 31) w0sum = x;
    __syncthreads();
    int excl = x - v + (wid ? w0sum : 0);
    if (tid < nblk) g_boff[tid] = excl;
    if (tid == 0) g_off[NN] = NE;
}
__global__ void k_scan3() {
    int i = blockIdx.x * blockDim.x + threadIdx.x;
    if (i >= NN) return;
    int o = g_off[i] + g_boff[i >> 10];
    g_off[i] = o;
    g_cur[i] = o;
}
__global__ void k_scatter(const int* __restrict__ src, const int* __restrict__ dst) {
    int e = blockIdx.x * blockDim.x + threadIdx.x;
    if (e >= NE) return;
    int pos = atomicAdd(&g_cur[dst[e]], 1);
    g_csrc[pos] = src[e];
}

// ---------------- tensor-core GEMM with fused input-LayerNorm+ReLU ----------------
// out = f(A)[N,128] @ W16[128,128] (+bias);  f = identity or relu(LN(.))
// PAIR: gridDim.y=2; y=0 -> half output houta (Wa16,ba); y=1 -> float output foutb (Wb16,bb)
template <bool LNIN, bool PAIR>
__global__ void __launch_bounds__(256) gemm128t(
        const float* __restrict__ A,
        const __half* __restrict__ Wa16, const float* __restrict__ ba, __half* __restrict__ houta,
        const __half* __restrict__ Wb16, const float* __restrict__ bb, float* __restrict__ foutb,
        int slot, const float* __restrict__ gm, const float* __restrict__ bt) {
    __shared__ __half Ah[128][136];
    __shared__ float stg[8][16][16];

    bool second = PAIR && (blockIdx.y != 0);
    const __half* W16  = second ? Wb16 : Wa16;
    const float*  bias = second ? bb : ba;

    int t = threadIdx.x;
    int row0 = blockIdx.x * 128;

    float fmu = 0.f, finv = 0.f;
    if (LNIN) {
        double mu = g_red[2 * slot] * (1.0 / (double)ND);
        double var = g_red[2 * slot + 1] * (1.0 / (double)ND) - mu * mu;
        fmu = (float)mu;
        finv = 1.0f / (sqrtf(fmaxf((float)var, 0.0f)) + EPSF);
    }

    // cooperative A-tile load: 128x128 fp32 -> LN/ReLU -> half smem
#pragma unroll
    for (int j = 0; j < 16; j++) {
        int f = t + j * 256;           // float4 index 0..4095
        int lin = f * 4;
        int r = lin >> 7, c = lin & 127;
        int gr = row0 + r;
        float4 v = (gr < NN) ? *(const float4*)(A + (size_t)gr * 128 + c)
                             : make_float4(0.f, 0.f, 0.f, 0.f);
        if (LNIN) {
            float4 gv = *(const float4*)(gm + c);
            float4 bv = *(const float4*)(bt + c);
            v.x = fmaxf((v.x - fmu) * finv * gv.x + bv.x, 0.f);
            v.y = fmaxf((v.y - fmu) * finv * gv.y + bv.y, 0.f);
            v.z = fmaxf((v.z - fmu) * finv * gv.z + bv.z, 0.f);
            v.w = fmaxf((v.w - fmu) * finv * gv.w + bv.w, 0.f);
        }
        __half2* dsth = (__half2*)&Ah[r][c];
        dsth[0] = __floats2half2_rn(v.x, v.y);
        dsth[1] = __floats2half2_rn(v.z, v.w);
    }
    __syncthreads();

    int w = t >> 5;            // warp id: rows w*16..w*16+15
    int lane = t & 31;

    wmma::fragment<wmma::accumulator, 16, 16, 16, float> acc[8];
#pragma unroll
    for (int n = 0; n < 8; n++) wmma::fill_fragment(acc[n], 0.0f);

#pragma unroll
    for (int k = 0; k < 8; k++) {
        wmma::fragment<wmma::matrix_a, 16, 16, 16, __half, wmma::row_major> af;
        wmma::load_matrix_sync(af, &Ah[w * 16][k * 16], 136);
#pragma unroll
        for (int n = 0; n < 8; n++) {
            wmma::fragment<wmma::matrix_b, 16, 16, 16, __half, wmma::row_major> bf;
            wmma::load_matrix_sync(bf, W16 + (size_t)(k * 16) * 128 + n * 16, 128);
            wmma::mma_sync(acc[n], af, bf, acc[n]);
        }
    }

    // epilogue: per-warp staging -> bias -> store (half or float)
    int row_in = lane >> 1;
    int csub = (lane & 1) * 8;
    int gr = row0 + w * 16 + row_in;
#pragma unroll
    for (int n = 0; n < 8; n++) {
        wmma::store_matrix_sync(&stg[w][0][0], acc[n], 16, wmma::mem_row_major);
        __syncwarp();
        if (gr < NN) {
            int colg = n * 16 + csub;
            float r[8];
#pragma unroll
            for (int q = 0; q < 8; q++) {
                r[q] = stg[w][row_in][csub + q];
                if (bias) r[q] += bias[colg + q];
            }
            if (second) {
                float* o = foutb + (size_t)gr * 128 + colg;
                *(float4*)(o)     = make_float4(r[0], r[1], r[2], r[3]);
                *(float4*)(o + 4) = make_float4(r[4], r[5], r[6], r[7]);
            } else {
                __half2 hh[4];
                hh[0] = __floats2half2_rn(r[0], r[1]);
                hh[1] = __floats2half2_rn(r[2], r[3]);
                hh[2] = __floats2half2_rn(r[4], r[5]);
                hh[3] = __floats2half2_rn(r[6], r[7]);
                *(uint4*)(houta + (size_t)gr * 128 + colg) = *(uint4*)hh;
            }
        }
        __syncwarp();
    }
}

// ---------------- block epilogue: fused LN partial reduction ----------------
__device__ __forceinline__ void ln_block_reduce(float s, float s2, int slot) {
#pragma unroll
    for (int o = 16; o; o >>= 1) {
        s  += __shfl_xor_sync(0xffffffffu, s, o);
        s2 += __shfl_xor_sync(0xffffffffu, s2, o);
    }
    __shared__ float shs[8], shs2[8];
    int wid = threadIdx.x >> 5, lane = threadIdx.x & 31;
    if (lane == 0) { shs[wid] = s; shs2[wid] = s2; }
    __syncthreads();
    if (threadIdx.x == 0) {
        double ts = 0.0, t2 = 0.0;
        int nw = blockDim.x >> 5;
        for (int k = 0; k < nw; k++) { ts += (double)shs[k]; t2 += (double)shs2[k]; }
        atomicAdd(&g_red[2 * slot], ts);
        atomicAdd(&g_red[2 * slot + 1], t2);
    }
}

__device__ __forceinline__ void load_h4(const __half* base, int node, int lane,
                                        float2& f0, float2& f1) {
    uint2 raw = *(const uint2*)(base + (size_t)node * 128 + lane * 4);
    f0 = __half22float2(*(__half2*)&raw.x);
    f1 = __half22float2(*(__half2*)&raw.y);
}

// ---------------- GCN aggregation (CSR gather, warp per node, chunk-8, fp16 src) ---
__global__ void __launch_bounds__(256) k_gcn_csr(const float* __restrict__ bias, int slot) {
    int w = (blockIdx.x * blockDim.x + threadIdx.x) >> 5;
    int lane = threadIdx.x & 31;
    float s = 0.f, s2 = 0.f;
    if (w < NN) {
        float dd = g_dinv[w];
        float2 v0, v1;
        load_h4(g_xwh, w, lane, v0, v1);
        float sf = dd * dd;
        float4 acc = make_float4(v0.x * sf, v0.y * sf, v1.x * sf, v1.y * sf);
        int b = g_off[w], e = g_off[w + 1];
        int i = b;
        for (; i + 8 <= e; i += 8) {
            int si[8];
#pragma unroll
            for (int j = 0; j < 8; j++) si[j] = g_csrc[i + j];
            uint2 raw[8];
#pragma unroll
            for (int j = 0; j < 8; j++)
                raw[j] = *(const uint2*)(g_xwh + (size_t)si[j] * 128 + lane * 4);
#pragma unroll
            for (int j = 0; j < 8; j++) {
                float nr = g_dinv[si[j]] * dd;
                float2 a = __half22float2(*(__half2*)&raw[j].x);
                float2 c = __half22float2(*(__half2*)&raw[j].y);
                acc.x += a.x * nr; acc.y += a.y * nr;
                acc.z += c.x * nr; acc.w += c.y * nr;
            }
        }
        for (; i < e; i++) {
            int sn = g_csrc[i];
            float nr = g_dinv[sn] * dd;
            float2 a0, a1;
            load_h4(g_xwh, sn, lane, a0, a1);
            acc.x += a0.x * nr; acc.y += a0.y * nr;
            acc.z += a1.x * nr; acc.w += a1.y * nr;
        }
        float4 b4 = ((const float4*)bias)[lane];
        acc.x += b4.x; acc.y += b4.y; acc.z += b4.z; acc.w += b4.w;
        ((float4*)(g_acc + (size_t)w * 128))[lane] = acc;
        s  = acc.x + acc.y + acc.z + acc.w;
        s2 = acc.x * acc.x + acc.y * acc.y + acc.z * acc.z + acc.w * acc.w;
    }
    ln_block_reduce(s, s2, slot);
}

// ---------------- fused GATv2 (CSR gather + online softmax, chunk-4, fp16 src) ----
template <int H>
__device__ __forceinline__ float head_score(float4 v, float4 r4, float4 a4) {
    float q = leaky(v.x + r4.x) * a4.x + leaky(v.y + r4.y) * a4.y +
              leaky(v.z + r4.z) * a4.z + leaky(v.w + r4.w) * a4.w;
    if (H == 8) {
        q += __shfl_xor_sync(0xffffffffu, q, 1);
        q += __shfl_xor_sync(0xffffffffu, q, 2);
    } else {
#pragma unroll
        for (int o = 16; o; o >>= 1) q += __shfl_xor_sync(0xffffffffu, q, o);
    }
    return q;
}

__device__ __forceinline__ float4 h4_to_f4(uint2 raw) {
    float2 a = __half22float2(*(__half2*)&raw.x);
    float2 b = __half22float2(*(__half2*)&raw.y);
    return make_float4(a.x, a.y, b.x, b.y);
}

template <int H>
__global__ void __launch_bounds__(256) k_gat_csr(const float* __restrict__ att,
                                                 const float* __restrict__ bias, int slot) {
    int w = (blockIdx.x * blockDim.x + threadIdx.x) >> 5;
    int lane = threadIdx.x & 31;
    float ps = 0.f, ps2 = 0.f;
    if (w < NN) {
        float4 r4 = ((const float4*)(g_xr + (size_t)w * 128))[lane];
        float4 a4 = ((const float4*)att)[lane];

        uint2 rawl = *(const uint2*)(g_xlh + (size_t)w * 128 + lane * 4);
        float4 l4 = h4_to_f4(rawl);
        float m = head_score<H>(l4, r4, a4);
        float den = 1.0f;
        float4 acc = l4;

        int b = g_off[w], e = g_off[w + 1];
        int i = b;
        for (; i + 4 <= e; i += 4) {
            int s0 = g_csrc[i], s1 = g_csrc[i + 1], s2 = g_csrc[i + 2], s3 = g_csrc[i + 3];
            uint2 w0r = *(const uint2*)(g_xlh + (size_t)s0 * 128 + lane * 4);
            uint2 w1r = *(const uint2*)(g_xlh + (size_t)s1 * 128 + lane * 4);
            uint2 w2r = *(const uint2*)(g_xlh + (size_t)s2 * 128 + lane * 4);
            uint2 w3r = *(const uint2*)(g_xlh + (size_t)s3 * 128 + lane * 4);
            float4 u0 = h4_to_f4(w0r), u1 = h4_to_f4(w1r);
            float4 u2 = h4_to_f4(w2r), u3 = h4_to_f4(w3r);
            float q0 = head_score<H>(u0, r4, a4);
            float q1 = head_score<H>(u1, r4, a4);
            float q2 = head_score<H>(u2, r4, a4);
            float q3 = head_score<H>(u3, r4, a4);
            float nm = fmaxf(fmaxf(fmaxf(q0, q1), fmaxf(q2, q3)), m);
            float so = __expf(m - nm);
            float w0 = __expf(q0 - nm), w1 = __expf(q1 - nm);
            float w2 = __expf(q2 - nm), w3 = __expf(q3 - nm);
            den = den * so + w0 + w1 + w2 + w3;
            acc.x = acc.x * so + u0.x * w0 + u1.x * w1 + u2.x * w2 + u3.x * w3;
            acc.y = acc.y * so + u0.y * w0 + u1.y * w1 + u2.y * w2 + u3.y * w3;
            acc.z = acc.z * so + u0.z * w0 + u1.z * w1 + u2.z * w2 + u3.z * w3;
            acc.w = acc.w * so + u0.w * w0 + u1.w * w1 + u2.w * w2 + u3.w * w3;
            m = nm;
        }
        for (; i < e; i++) {
            int sn = g_csrc[i];
            uint2 vr = *(const uint2*)(g_xlh + (size_t)sn * 128 + lane * 4);
            float4 v = h4_to_f4(vr);
            float q = head_score<H>(v, r4, a4);
            float nm = fmaxf(m, q);
            float so = __expf(m - nm);
            float wg = __expf(q - nm);
            den = den * so + wg;
            acc.x = acc.x * so + v.x * wg;
            acc.y = acc.y * so + v.y * wg;
            acc.z = acc.z * so + v.z * wg;
            acc.w = acc.w * so + v.w * wg;
            m = nm;
        }
        float inv = 1.0f / den;
        float4 b4 = ((const float4*)bias)[lane];
        acc.x = acc.x * inv + b4.x;
        acc.y = acc.y * inv + b4.y;
        acc.z = acc.z * inv + b4.z;
        acc.w = acc.w * inv + b4.w;
        ((float4*)(g_acc + (size_t)w * 128))[lane] = acc;
        ps  = acc.x + acc.y + acc.z + acc.w;
        ps2 = acc.x * acc.x + acc.y * acc.y + acc.z * acc.z + acc.w * acc.w;
    }
    ln_block_reduce(ps, ps2, slot);
}

// ---------------- LayerNorm apply (final layer only) ----------------
__global__ void k_ln_apply(const float* __restrict__ in,
                           const float* __restrict__ gm, const float* __restrict__ bt,
                           float* __restrict__ out, int slot) {
    int i = blockIdx.x * blockDim.x + threadIdx.x;
    if (i >= ND) return;
    double mu = g_red[2 * slot] * (1.0 / (double)ND);
    double var = g_red[2 * slot + 1] * (1.0 / (double)ND) - mu * mu;
    float inv = 1.0f / (sqrtf(fmaxf((float)var, 0.0f)) + EPSF);
    int c = i & 127;
    float v = in[i];
    out[i] = (v - (float)mu) * inv * gm[c] + bt[c];
}

// ---------------- launch ----------------
static inline int gridFor(long long n, int blk) { return (int)((n + blk - 1) / blk); }

extern "C" void kernel_launch(void* const* d_in, const int* in_sizes, int n_in,
                              void* d_out, int out_size) {
    const float* x   = (const float*)d_in[0];
    const int*   ei  = (const int*)d_in[1];
    const float* W0  = (const float*)d_in[2];
    const float* b0  = (const float*)d_in[3];
    const float* g0  = (const float*)d_in[4];
    const float* be0 = (const float*)d_in[5];
    const float* Wl1 = (const float*)d_in[6];
    const float* bl1 = (const float*)d_in[7];
    const float* Wr1 = (const float*)d_in[8];
    const float* br1 = (const float*)d_in[9];
    const float* att1= (const float*)d_in[10];
    const float* bg1 = (const float*)d_in[11];
    const float* g1  = (const float*)d_in[12];
    const float* be1 = (const float*)d_in[13];
    const float* W2  = (const float*)d_in[14];
    const float* b2  = (const float*)d_in[15];
    const float* g2  = (const float*)d_in[16];
    const float* be2 = (const float*)d_in[17];
    const float* Wl3 = (const float*)d_in[18];
    const float* bl3 = (const float*)d_in[19];
    const float* Wr3 = (const float*)d_in[20];
    const float* br3 = (const float*)d_in[21];
    const float* att3= (const float*)d_in[22];
    const float* bg3 = (const float*)d_in[23];
    const float* g3  = (const float*)d_in[24];
    const float* be3 = (const float*)d_in[25];
    float* out = (float*)d_out;

    const int* src = ei;
    const int* dst = ei + NE;

    const int BLK = 256;
    const int gN   = gridFor(NN, BLK);
    const int gE   = gridFor(NE, BLK);
    const int gND  = gridFor(ND, BLK);
    const int gNW  = gridFor((long long)NN * 32, BLK);
    const int nGemmX = gridFor(NN, 128);
    const dim3 gG1(nGemmX, 1), gG2(nGemmX, 2);
    const int nScanBlk = gridFor(NN, 1024);

    __half* p_xwh; cudaGetSymbolAddress((void**)&p_xwh, g_xwh);
    __half* p_xlh; cudaGetSymbolAddress((void**)&p_xlh, g_xlh);
    float* p_xr;  cudaGetSymbolAddress((void**)&p_xr, g_xr);
    float* p_acc; cudaGetSymbolAddress((void**)&p_acc, g_acc);
    __half* p_wh; cudaGetSymbolAddress((void**)&p_wh, g_wh);

    const __half* w0h  = p_wh;
    const __half* wl1h = p_wh + 1 * DD * DD;
    const __half* wr1h = p_wh + 2 * DD * DD;
    const __half* w2h  = p_wh + 3 * DD * DD;
    const __half* wl3h = p_wh + 4 * DD * DD;
    const __half* wr3h = p_wh + 5 * DD * DD;

    // launches 1-3: CSR front + weight conversion; launch 4 = tensor GEMM (ncu target)
    k_hist_zero<<<gN, BLK>>>();
    k_hist<<<gE, BLK>>>(dst);
    k_cvt_w<<<dim3(gridFor(DD * DD, BLK), 6), BLK>>>(W0, Wl1, Wr1, W2, Wl3, Wr3);
    gemm128t<false, false><<<gG1, BLK>>>(x, w0h, nullptr, p_xwh,
                                         nullptr, nullptr, nullptr, 0, nullptr, nullptr);

    k_scan1<<<nScanBlk, 1024>>>();
    k_scan2<<<1, 64>>>(nScanBlk);
    k_scan3<<<gN, BLK>>>();
    k_scatter<<<gE, BLK>>>(src, dst);

    // ---- layer 0: GCN agg (bias fused, LN stats slot 0) ----
    k_gcn_csr<<<gNW, BLK>>>(b0, 0);

    // ---- layer 1: GATv2 (H=8) ----
    gemm128t<true, true><<<gG2, BLK>>>(p_acc, wl1h, bl1, p_xlh,
                                       wr1h, br1, p_xr, 0, g0, be0);
    k_gat_csr<8><<<gNW, BLK>>>(att1, bg1, 1);

    // ---- layer 2: GCN ----
    gemm128t<true, false><<<gG1, BLK>>>(p_acc, w2h, nullptr, p_xwh,
                                        nullptr, nullptr, nullptr, 1, g1, be1);
    k_gcn_csr<<<gNW, BLK>>>(b2, 2);

    // ---- layer 3: GATv2 (H=1) ----
    gemm128t<true, true><<<gG2, BLK>>>(p_acc, wl3h, bl3, p_xlh,
                                       wr3h, br3, p_xr, 2, g2, be2);
    k_gat_csr<1><<<gNW, BLK>>>(att3, bg3, 3);

    // ---- final LN -> output ----
    k_ln_apply<<<gND, BLK>>>(p_acc, g3, be3, out, 3);
}

// round 9
// speedup vs baseline: 5.3452x; 1.4383x over previous
#include <cuda_runtime.h>
#include <cuda_fp16.h>
#include <mma.h>
#include <math.h>
#include <stdint.h>

using namespace nvcuda;

#define NN 50000
#define NE 800000
#define DD 128
#define ND (NN * DD)
#define EPSF 1e-5f
#define NEGS 0.2f

// dynamic smem layout for gemm128t:
//   phase 1 (MMA):   Ah  = half[128][136]  @ 0        (34816 B)
//                    Wsh = half[128][136]  @ 34816    (34816 B)
//   phase 2 (epi):   stage = float[8][16][136] @ 0    (69632 B, aliases phase 1)
#define GEMM_SMEM 69632

// ---------------- scratch (static device globals; no allocation) ----------------
__device__ __half g_xwh[ND];    // GCN transform (half, gather payload)
__device__ __half g_xlh[ND];    // GAT left transform (half, gather payload)
__device__ float g_xr[ND];      // GAT right transform (fp32)
__device__ float g_acc[ND];     // aggregation output (bias added, pre-LN, fp32)
__device__ __half g_wh[6 * DD * DD];  // fp16 weight copies
__device__ float g_dinv[NN];    // deg^{-1/2}
__device__ int   g_cnt[NN];     // in-degree histogram (no self loop)
__device__ int   g_off[NN + 1]; // CSR offsets
__device__ int   g_cur[NN];     // scatter cursors
__device__ int   g_csrc[NE];    // CSR: src node per incoming edge
__device__ int   g_bsum[64];    // scan block totals
__device__ int   g_boff[64];    // scan block offsets
__device__ double g_red[8];     // (sum,sumsq) x 4 LN slots

__device__ __forceinline__ float leaky(float v) {
    return v > 0.0f ? v : NEGS * v;
}

// ---------------- weight conversion (fp32 -> fp16, all 6 matrices) ----------------
__global__ void k_cvt_w(const float* __restrict__ w0, const float* __restrict__ w1,
                        const float* __restrict__ w2, const float* __restrict__ w3,
                        const float* __restrict__ w4, const float* __restrict__ w5) {
    const float* ws[6] = {w0, w1, w2, w3, w4, w5};
    int m = blockIdx.y;
    int i = blockIdx.x * blockDim.x + threadIdx.x;
    if (i < DD * DD) g_wh[m * DD * DD + i] = __float2half_rn(ws[m][i]);
}

// ---------------- CSR build ----------------
__global__ void k_hist_zero() {
    int i = blockIdx.x * blockDim.x + threadIdx.x;
    if (i < NN) g_cnt[i] = 0;
    if (i < 8) g_red[i] = 0.0;
}
__global__ void k_hist(const int* __restrict__ dst) {
    int e = blockIdx.x * blockDim.x + threadIdx.x;
    if (e < NE) atomicAdd(&g_cnt[dst[e]], 1);
}
__global__ void k_scan1() {
    __shared__ int warp_sums[32];
    int tid = threadIdx.x;
    int lane = tid & 31, wid = tid >> 5;
    int i = blockIdx.x * 1024 + tid;
    int v = (i < NN) ? g_cnt[i] : 0;
    int x = v;
#pragma unroll
    for (int o = 1; o < 32; o <<= 1) {
        int y = __shfl_up_sync(0xffffffffu, x, o);
        if (lane >= o) x += y;
    }
    if (lane == 31) warp_sums[wid] = x;
    __syncthreads();
    if (wid == 0) {
        int ws = warp_sums[lane];
#pragma unroll
        for (int o = 1; o < 32; o <<= 1) {
            int y = __shfl_up_sync(0xffffffffu, ws, o);
            if (lane >= o) ws += y;
        }
        warp_sums[lane] = ws;
    }
    __syncthreads();
    int incl = x + (wid ? warp_sums[wid - 1] : 0);
    if (i < NN) {
        g_off[i] = incl - v;
        g_dinv[i] = rsqrtf((float)v + 1.0f);
    }
    if (tid == 1023) g_bsum[blockIdx.x] = incl;
}
__global__ void k_scan2(int nblk) {
    __shared__ int w0sum;
    int tid = threadIdx.x;
    int lane = tid & 31, wid = tid >> 5;
    int v = (tid < nblk) ? g_bsum[tid] : 0;
    int x = v;
#pragma unroll
    for (int o = 1; o < 32; o <<= 1) {
        int y = __shfl_up_sync(0xffffffffu, x, o);
        if (lane >= o) x += y;
    }
    if (tid == 31) w0sum = x;
    __syncthreads();
    int excl = x - v + (wid ? w0sum : 0);
    if (tid < nblk) g_boff[tid] = excl;
    if (tid == 0) g_off[NN] = NE;
}
__global__ void k_scan3() {
    int i = blockIdx.x * blockDim.x + threadIdx.x;
    if (i >= NN) return;
    int o = g_off[i] + g_boff[i >> 10];
    g_off[i] = o;
    g_cur[i] = o;
}
__global__ void k_scatter(const int* __restrict__ src, const int* __restrict__ dst) {
    int e = blockIdx.x * blockDim.x + threadIdx.x;
    if (e >= NE) return;
    int pos = atomicAdd(&g_cur[dst[e]], 1);
    g_csrc[pos] = src[e];
}

// ---------------- tensor-core GEMM with fused input-LayerNorm+ReLU ----------------
// out = f(A)[N,128] @ W16[128,128] (+bias);  f = identity or relu(LN(.))
// PAIR: gridDim.y=2; y=0 -> half output houta (Wa16,ba); y=1 -> float output foutb
template <bool LNIN, bool PAIR>
__global__ void __launch_bounds__(256) gemm128t(
        const float* __restrict__ A,
        const __half* __restrict__ Wa16, const float* __restrict__ ba, __half* __restrict__ houta,
        const __half* __restrict__ Wb16, const float* __restrict__ bb, float* __restrict__ foutb,
        int slot, const float* __restrict__ gm, const float* __restrict__ bt) {
    extern __shared__ char smem[];
    __half (*Ah)[136]  = (__half(*)[136])smem;
    __half (*Wsh)[136] = (__half(*)[136])(smem + 34816);

    bool second = PAIR && (blockIdx.y != 0);
    const __half* W16  = second ? Wb16 : Wa16;
    const float*  bias = second ? bb : ba;

    int t = threadIdx.x;
    int row0 = blockIdx.x * 128;

    float fmu = 0.f, finv = 0.f;
    if (LNIN) {
        double mu = g_red[2 * slot] * (1.0 / (double)ND);
        double var = g_red[2 * slot + 1] * (1.0 / (double)ND) - mu * mu;
        fmu = (float)mu;
        finv = 1.0f / (sqrtf(fmaxf((float)var, 0.0f)) + EPSF);
    }

    // stage W (128x128 half) into shared, coalesced uint4 (8 halfs each)
#pragma unroll
    for (int j = 0; j < 8; j++) {
        int u = t + j * 256;            // uint4 index 0..2047
        int lin = u * 8;                // half index
        int r = lin >> 7, c = lin & 127;
        *(uint4*)&Wsh[r][c] = *(const uint4*)(W16 + (size_t)r * 128 + c);
    }

    // stage A tile: 128x128 fp32 -> LN/ReLU -> half smem
#pragma unroll
    for (int j = 0; j < 16; j++) {
        int f = t + j * 256;           // float4 index 0..4095
        int lin = f * 4;
        int r = lin >> 7, c = lin & 127;
        int gr = row0 + r;
        float4 v = (gr < NN) ? *(const float4*)(A + (size_t)gr * 128 + c)
                             : make_float4(0.f, 0.f, 0.f, 0.f);
        if (LNIN) {
            float4 gv = *(const float4*)(gm + c);
            float4 bv = *(const float4*)(bt + c);
            v.x = fmaxf((v.x - fmu) * finv * gv.x + bv.x, 0.f);
            v.y = fmaxf((v.y - fmu) * finv * gv.y + bv.y, 0.f);
            v.z = fmaxf((v.z - fmu) * finv * gv.z + bv.z, 0.f);
            v.w = fmaxf((v.w - fmu) * finv * gv.w + bv.w, 0.f);
        }
        __half2* dsth = (__half2*)&Ah[r][c];
        dsth[0] = __floats2half2_rn(v.x, v.y);
        dsth[1] = __floats2half2_rn(v.z, v.w);
    }
    __syncthreads();

    int w = t >> 5;            // warp id: rows w*16..w*16+15
    int lane = t & 31;

    wmma::fragment<wmma::accumulator, 16, 16, 16, float> acc[8];
#pragma unroll
    for (int n = 0; n < 8; n++) wmma::fill_fragment(acc[n], 0.0f);

#pragma unroll
    for (int k = 0; k < 8; k++) {
        wmma::fragment<wmma::matrix_a, 16, 16, 16, __half, wmma::row_major> af;
        wmma::load_matrix_sync(af, &Ah[w * 16][k * 16], 136);
#pragma unroll
        for (int n = 0; n < 8; n++) {
            wmma::fragment<wmma::matrix_b, 16, 16, 16, __half, wmma::row_major> bf;
            wmma::load_matrix_sync(bf, &Wsh[k * 16][n * 16], 136);
            wmma::mma_sync(acc[n], af, bf, acc[n]);
        }
    }
    __syncthreads();   // done with Ah/Wsh; reuse smem for epilogue staging

    // epilogue: per-warp contiguous 16x136 float staging, then coalesced sweep
    float* stage = (float*)smem + (size_t)w * (16 * 136);
#pragma unroll
    for (int n = 0; n < 8; n++)
        wmma::store_matrix_sync(stage + n * 16, acc[n], 136, wmma::mem_row_major);
    __syncwarp();

    int row_in = lane >> 1;
    int c0 = (lane & 1) * 64;
    int gr = row0 + w * 16 + row_in;
    if (gr < NN) {
#pragma unroll
        for (int q = 0; q < 64; q += 8) {
            int colg = c0 + q;
            float4 v0 = *(float4*)(stage + row_in * 136 + colg);
            float4 v1 = *(float4*)(stage + row_in * 136 + colg + 4);
            if (bias) {
                float4 b0 = *(const float4*)(bias + colg);
                float4 b1 = *(const float4*)(bias + colg + 4);
                v0.x += b0.x; v0.y += b0.y; v0.z += b0.z; v0.w += b0.w;
                v1.x += b1.x; v1.y += b1.y; v1.z += b1.z; v1.w += b1.w;
            }
            if (second) {
                float* o = foutb + (size_t)gr * 128 + colg;
                *(float4*)(o)     = v0;
                *(float4*)(o + 4) = v1;
            } else {
                __half2 hh[4];
                hh[0] = __floats2half2_rn(v0.x, v0.y);
                hh[1] = __floats2half2_rn(v0.z, v0.w);
                hh[2] = __floats2half2_rn(v1.x, v1.y);
                hh[3] = __floats2half2_rn(v1.z, v1.w);
                *(uint4*)(houta + (size_t)gr * 128 + colg) = *(uint4*)hh;
            }
        }
    }
}

// ---------------- block epilogue: fused LN partial reduction ----------------
__device__ __forceinline__ void ln_block_reduce(float s, float s2, int slot) {
#pragma unroll
    for (int o = 16; o; o >>= 1) {
        s  += __shfl_xor_sync(0xffffffffu, s, o);
        s2 += __shfl_xor_sync(0xffffffffu, s2, o);
    }
    __shared__ float shs[8], shs2[8];
    int wid = threadIdx.x >> 5, lane = threadIdx.x & 31;
    if (lane == 0) { shs[wid] = s; shs2[wid] = s2; }
    __syncthreads();
    if (threadIdx.x == 0) {
        double ts = 0.0, t2 = 0.0;
        int nw = blockDim.x >> 5;
        for (int k = 0; k < nw; k++) { ts += (double)shs[k]; t2 += (double)shs2[k]; }
        atomicAdd(&g_red[2 * slot], ts);
        atomicAdd(&g_red[2 * slot + 1], t2);
    }
}

__device__ __forceinline__ void load_h4(const __half* base, int node, int lane,
                                        float2& f0, float2& f1) {
    uint2 raw = *(const uint2*)(base + (size_t)node * 128 + lane * 4);
    f0 = __half22float2(*(__half2*)&raw.x);
    f1 = __half22float2(*(__half2*)&raw.y);
}

// ---------------- GCN aggregation (CSR gather, warp per node, chunk-8, fp16 src) ---
__global__ void __launch_bounds__(256) k_gcn_csr(const float* __restrict__ bias, int slot) {
    int w = (blockIdx.x * blockDim.x + threadIdx.x) >> 5;
    int lane = threadIdx.x & 31;
    float s = 0.f, s2 = 0.f;
    if (w < NN) {
        float dd = g_dinv[w];
        float2 v0, v1;
        load_h4(g_xwh, w, lane, v0, v1);
        float sf = dd * dd;
        float4 acc = make_float4(v0.x * sf, v0.y * sf, v1.x * sf, v1.y * sf);
        int b = g_off[w], e = g_off[w + 1];
        int i = b;
        for (; i + 8 <= e; i += 8) {
            int si[8];
#pragma unroll
            for (int j = 0; j < 8; j++) si[j] = g_csrc[i + j];
            uint2 raw[8];
#pragma unroll
            for (int j = 0; j < 8; j++)
                raw[j] = *(const uint2*)(g_xwh + (size_t)si[j] * 128 + lane * 4);
#pragma unroll
            for (int j = 0; j < 8; j++) {
                float nr = g_dinv[si[j]] * dd;
                float2 a = __half22float2(*(__half2*)&raw[j].x);
                float2 c = __half22float2(*(__half2*)&raw[j].y);
                acc.x += a.x * nr; acc.y += a.y * nr;
                acc.z += c.x * nr; acc.w += c.y * nr;
            }
        }
        for (; i < e; i++) {
            int sn = g_csrc[i];
            float nr = g_dinv[sn] * dd;
            float2 a0, a1;
            load_h4(g_xwh, sn, lane, a0, a1);
            acc.x += a0.x * nr; acc.y += a0.y * nr;
            acc.z += a1.x * nr; acc.w += a1.y * nr;
        }
        float4 b4 = ((const float4*)bias)[lane];
        acc.x += b4.x; acc.y += b4.y; acc.z += b4.z; acc.w += b4.w;
        ((float4*)(g_acc + (size_t)w * 128))[lane] = acc;
        s  = acc.x + acc.y + acc.z + acc.w;
        s2 = acc.x * acc.x + acc.y * acc.y + acc.z * acc.z + acc.w * acc.w;
    }
    ln_block_reduce(s, s2, slot);
}

// ---------------- fused GATv2 (CSR gather + online softmax, chunk-4, fp16 src) ----
template <int H>
__device__ __forceinline__ float head_score(float4 v, float4 r4, float4 a4) {
    float q = leaky(v.x + r4.x) * a4.x + leaky(v.y + r4.y) * a4.y +
              leaky(v.z + r4.z) * a4.z + leaky(v.w + r4.w) * a4.w;
    if (H == 8) {
        q += __shfl_xor_sync(0xffffffffu, q, 1);
        q += __shfl_xor_sync(0xffffffffu, q, 2);
    } else {
#pragma unroll
        for (int o = 16; o; o >>= 1) q += __shfl_xor_sync(0xffffffffu, q, o);
    }
    return q;
}

__device__ __forceinline__ float4 h4_to_f4(uint2 raw) {
    float2 a = __half22float2(*(__half2*)&raw.x);
    float2 b = __half22float2(*(__half2*)&raw.y);
    return make_float4(a.x, a.y, b.x, b.y);
}

template <int H>
__global__ void __launch_bounds__(256) k_gat_csr(const float* __restrict__ att,
                                                 const float* __restrict__ bias, int slot) {
    int w = (blockIdx.x * blockDim.x + threadIdx.x) >> 5;
    int lane = threadIdx.x & 31;
    float ps = 0.f, ps2 = 0.f;
    if (w < NN) {
        float4 r4 = ((const float4*)(g_xr + (size_t)w * 128))[lane];
        float4 a4 = ((const float4*)att)[lane];

        uint2 rawl = *(const uint2*)(g_xlh + (size_t)w * 128 + lane * 4);
        float4 l4 = h4_to_f4(rawl);
        float m = head_score<H>(l4, r4, a4);
        float den = 1.0f;
        float4 acc = l4;

        int b = g_off[w], e = g_off[w + 1];
        int i = b;
        for (; i + 4 <= e; i += 4) {
            int s0 = g_csrc[i], s1 = g_csrc[i + 1], s2 = g_csrc[i + 2], s3 = g_csrc[i + 3];
            uint2 w0r = *(const uint2*)(g_xlh + (size_t)s0 * 128 + lane * 4);
            uint2 w1r = *(const uint2*)(g_xlh + (size_t)s1 * 128 + lane * 4);
            uint2 w2r = *(const uint2*)(g_xlh + (size_t)s2 * 128 + lane * 4);
            uint2 w3r = *(const uint2*)(g_xlh + (size_t)s3 * 128 + lane * 4);
            float4 u0 = h4_to_f4(w0r), u1 = h4_to_f4(w1r);
            float4 u2 = h4_to_f4(w2r), u3 = h4_to_f4(w3r);
            float q0 = head_score<H>(u0, r4, a4);
            float q1 = head_score<H>(u1, r4, a4);
            float q2 = head_score<H>(u2, r4, a4);
            float q3 = head_score<H>(u3, r4, a4);
            float nm = fmaxf(fmaxf(fmaxf(q0, q1), fmaxf(q2, q3)), m);
            float so = __expf(m - nm);
            float w0 = __expf(q0 - nm), w1 = __expf(q1 - nm);
            float w2 = __expf(q2 - nm), w3 = __expf(q3 - nm);
            den = den * so + w0 + w1 + w2 + w3;
            acc.x = acc.x * so + u0.x * w0 + u1.x * w1 + u2.x * w2 + u3.x * w3;
            acc.y = acc.y * so + u0.y * w0 + u1.y * w1 + u2.y * w2 + u3.y * w3;
            acc.z = acc.z * so + u0.z * w0 + u1.z * w1 + u2.z * w2 + u3.z * w3;
            acc.w = acc.w * so + u0.w * w0 + u1.w * w1 + u2.w * w2 + u3.w * w3;
            m = nm;
        }
        for (; i < e; i++) {
            int sn = g_csrc[i];
            uint2 vr = *(const uint2*)(g_xlh + (size_t)sn * 128 + lane * 4);
            float4 v = h4_to_f4(vr);
            float q = head_score<H>(v, r4, a4);
            float nm = fmaxf(m, q);
            float so = __expf(m - nm);
            float wg = __expf(q - nm);
            den = den * so + wg;
            acc.x = acc.x * so + v.x * wg;
            acc.y = acc.y * so + v.y * wg;
            acc.z = acc.z * so + v.z * wg;
            acc.w = acc.w * so + v.w * wg;
            m = nm;
        }
        float inv = 1.0f / den;
        float4 b4 = ((const float4*)bias)[lane];
        acc.x = acc.x * inv + b4.x;
        acc.y = acc.y * inv + b4.y;
        acc.z = acc.z * inv + b4.z;
        acc.w = acc.w * inv + b4.w;
        ((float4*)(g_acc + (size_t)w * 128))[lane] = acc;
        ps  = acc.x + acc.y + acc.z + acc.w;
        ps2 = acc.x * acc.x + acc.y * acc.y + acc.z * acc.z + acc.w * acc.w;
    }
    ln_block_reduce(ps, ps2, slot);
}

// ---------------- LayerNorm apply (final layer only) ----------------
__global__ void k_ln_apply(const float* __restrict__ in,
                           const float* __restrict__ gm, const float* __restrict__ bt,
                           float* __restrict__ out, int slot) {
    int i = blockIdx.x * blockDim.x + threadIdx.x;
    if (i >= ND) return;
    double mu = g_red[2 * slot] * (1.0 / (double)ND);
    double var = g_red[2 * slot + 1] * (1.0 / (double)ND) - mu * mu;
    float inv = 1.0f / (sqrtf(fmaxf((float)var, 0.0f)) + EPSF);
    int c = i & 127;
    float v = in[i];
    out[i] = (v - (float)mu) * inv * gm[c] + bt[c];
}

// ---------------- launch ----------------
static inline int gridFor(long long n, int blk) { return (int)((n + blk - 1) / blk); }

extern "C" void kernel_launch(void* const* d_in, const int* in_sizes, int n_in,
                              void* d_out, int out_size) {
    const float* x   = (const float*)d_in[0];
    const int*   ei  = (const int*)d_in[1];
    const float* W0  = (const float*)d_in[2];
    const float* b0  = (const float*)d_in[3];
    const float* g0  = (const float*)d_in[4];
    const float* be0 = (const float*)d_in[5];
    const float* Wl1 = (const float*)d_in[6];
    const float* bl1 = (const float*)d_in[7];
    const float* Wr1 = (const float*)d_in[8];
    const float* br1 = (const float*)d_in[9];
    const float* att1= (const float*)d_in[10];
    const float* bg1 = (const float*)d_in[11];
    const float* g1  = (const float*)d_in[12];
    const float* be1 = (const float*)d_in[13];
    const float* W2  = (const float*)d_in[14];
    const float* b2  = (const float*)d_in[15];
    const float* g2  = (const float*)d_in[16];
    const float* be2 = (const float*)d_in[17];
    const float* Wl3 = (const float*)d_in[18];
    const float* bl3 = (const float*)d_in[19];
    const float* Wr3 = (const float*)d_in[20];
    const float* br3 = (const float*)d_in[21];
    const float* att3= (const float*)d_in[22];
    const float* bg3 = (const float*)d_in[23];
    const float* g3  = (const float*)d_in[24];
    const float* be3 = (const float*)d_in[25];
    float* out = (float*)d_out;

    const int* src = ei;
    const int* dst = ei + NE;

    const int BLK = 256;
    const int gN   = gridFor(NN, BLK);
    const int gE   = gridFor(NE, BLK);
    const int gND  = gridFor(ND, BLK);
    const int gNW  = gridFor((long long)NN * 32, BLK);
    const int nGemmX = gridFor(NN, 128);
    const dim3 gG1(nGemmX, 1), gG2(nGemmX, 2);
    const int nScanBlk = gridFor(NN, 1024);

    __half* p_xwh; cudaGetSymbolAddress((void**)&p_xwh, g_xwh);
    __half* p_xlh; cudaGetSymbolAddress((void**)&p_xlh, g_xlh);
    float* p_xr;  cudaGetSymbolAddress((void**)&p_xr, g_xr);
    float* p_acc; cudaGetSymbolAddress((void**)&p_acc, g_acc);
    __half* p_wh; cudaGetSymbolAddress((void**)&p_wh, g_wh);

    const __half* w0h  = p_wh;
    const __half* wl1h = p_wh + 1 * DD * DD;
    const __half* wr1h = p_wh + 2 * DD * DD;
    const __half* w2h  = p_wh + 3 * DD * DD;
    const __half* wl3h = p_wh + 4 * DD * DD;
    const __half* wr3h = p_wh + 5 * DD * DD;

    // allow large dynamic smem for the 3 gemm instantiations (host-side, idempotent)
    static bool attr_done = false;
    if (!attr_done) {
        cudaFuncSetAttribute(gemm128t<false, false>,
                             cudaFuncAttributeMaxDynamicSharedMemorySize, GEMM_SMEM);
        cudaFuncSetAttribute(gemm128t<true, false>,
                             cudaFuncAttributeMaxDynamicSharedMemorySize, GEMM_SMEM);
        cudaFuncSetAttribute(gemm128t<true, true>,
                             cudaFuncAttributeMaxDynamicSharedMemorySize, GEMM_SMEM);
        attr_done = true;
    }

    // launches 1-3: CSR front + weight conversion; launch 4 = tensor GEMM (ncu target)
    k_hist_zero<<<gN, BLK>>>();
    k_hist<<<gE, BLK>>>(dst);
    k_cvt_w<<<dim3(gridFor(DD * DD, BLK), 6), BLK>>>(W0, Wl1, Wr1, W2, Wl3, Wr3);
    gemm128t<false, false><<<gG1, BLK, GEMM_SMEM>>>(x, w0h, nullptr, p_xwh,
                                                    nullptr, nullptr, nullptr, 0, nullptr, nullptr);

    k_scan1<<<nScanBlk, 1024>>>();
    k_scan2<<<1, 64>>>(nScanBlk);
    k_scan3<<<gN, BLK>>>();
    k_scatter<<<gE, BLK>>>(src, dst);

    // ---- layer 0: GCN agg (bias fused, LN stats slot 0) ----
    k_gcn_csr<<<gNW, BLK>>>(b0, 0);

    // ---- layer 1: GATv2 (H=8) ----
    gemm128t<true, true><<<gG2, BLK, GEMM_SMEM>>>(p_acc, wl1h, bl1, p_xlh,
                                                  wr1h, br1, p_xr, 0, g0, be0);
    k_gat_csr<8><<<gNW, BLK>>>(att1, bg1, 1);

    // ---- layer 2: GCN ----
    gemm128t<true, false><<<gG1, BLK, GEMM_SMEM>>>(p_acc, w2h, nullptr, p_xwh,
                                                   nullptr, nullptr, nullptr, 1, g1, be1);
    k_gcn_csr<<<gNW, BLK>>>(b2, 2);

    // ---- layer 3: GATv2 (H=1) ----
    gemm128t<true, true><<<gG2, BLK, GEMM_SMEM>>>(p_acc, wl3h, bl3, p_xlh,
                                                  wr3h, br3, p_xr, 2, g2, be2);
    k_gat_csr<1><<<gNW, BLK>>>(att3, bg3, 3);

    // ---- final LN -> output ----
    k_ln_apply<<<gND, BLK>>>(p_acc, g3, be3, out, 3);
}

// round 10
// speedup vs baseline: 5.3457x; 1.0001x over previous
#include <cuda_runtime.h>
#include <cuda_fp16.h>
#include <mma.h>
#include <math.h>
#include <stdint.h>

using namespace nvcuda;

#define NN 50000
#define NE 800000
#define DD 128
#define ND (NN * DD)
#define EPSF 1e-5f
#define NEGS 0.2f

#define GEMM_SMEM 69632

// ---------------- scratch (static device globals; no allocation) ----------------
__device__ __half g_xwh[ND];    // GCN transform (half, gather payload)
__device__ __half g_xlh[ND];    // GAT left transform (half, gather payload)
__device__ float g_xr[ND];      // GAT right transform (fp32)
__device__ float g_acc[ND];     // aggregation output (bias added, pre-LN, fp32)
__device__ __half g_wh[6 * DD * DD];  // fp16 weight copies
__device__ float g_dinv[NN];    // deg^{-1/2}
__device__ int   g_cnt[NN];     // in-degree histogram (no self loop)
__device__ int   g_off[NN + 1]; // CSR offsets
__device__ int   g_cur[NN];     // scatter cursors
__device__ int   g_csrc[NE];    // CSR: src node per incoming edge
__device__ int   g_bsum[64];    // scan block totals
__device__ double g_red[8];     // (sum,sumsq) x 4 LN slots

typedef unsigned long long ull;

// ---------------- packed f32x2 helpers (Blackwell; PTX-only ops) ----------------
__device__ __forceinline__ ull pk2(float a, float b) {
    ull r; asm("mov.b64 %0, {%1, %2};" : "=l"(r) : "f"(a), "f"(b)); return r;
}
__device__ __forceinline__ void upk2(ull p, float& a, float& b) {
    asm("mov.b64 {%0, %1}, %2;" : "=f"(a), "=f"(b) : "l"(p));
}
__device__ __forceinline__ ull fma2(ull a, ull b, ull c) {
    ull r; asm("fma.rn.f32x2 %0, %1, %2, %3;" : "=l"(r) : "l"(a), "l"(b), "l"(c)); return r;
}
__device__ __forceinline__ ull mul2p(ull a, ull b) {
    ull r; asm("mul.rn.f32x2 %0, %1, %2;" : "=l"(r) : "l"(a), "l"(b)); return r;
}
__device__ __forceinline__ ull add2p(ull a, ull b) {
    ull r; asm("add.rn.f32x2 %0, %1, %2;" : "=l"(r) : "l"(a), "l"(b)); return r;
}
__device__ __forceinline__ ull abs2p(ull a) {
    ull r; asm("and.b64 %0, %1, 0x7FFFFFFF7FFFFFFF;" : "=l"(r) : "l"(a)); return r;
}
// convert uint2 of 4 halfs -> two packed f32x2
__device__ __forceinline__ void h4_to_2x2(uint2 raw, ull& p01, ull& p23) {
    float2 a = __half22float2(*(__half2*)&raw.x);
    float2 b = __half22float2(*(__half2*)&raw.y);
    p01 = pk2(a.x, a.y); p23 = pk2(b.x, b.y);
}

// ---------------- fused init: zero hist + LN slots, convert weights ------------
__global__ void k_init(const float* __restrict__ w0, const float* __restrict__ w1,
                       const float* __restrict__ w2, const float* __restrict__ w3,
                       const float* __restrict__ w4, const float* __restrict__ w5) {
    int i = blockIdx.x * blockDim.x + threadIdx.x;
    if (i < NN) g_cnt[i] = 0;
    if (i < 8) g_red[i] = 0.0;
    if (i < 6 * DD * DD) {
        const float* ws[6] = {w0, w1, w2, w3, w4, w5};
        int m = i >> 14;           // / 16384
        int o = i & 16383;
        g_wh[i] = __float2half_rn(ws[m][o]);
    }
}
__global__ void k_hist(const int* __restrict__ dst) {
    int e = blockIdx.x * blockDim.x + threadIdx.x;
    if (e < NE) atomicAdd(&g_cnt[dst[e]], 1);
}
__global__ void k_scan1() {
    __shared__ int warp_sums[32];
    int tid = threadIdx.x;
    int lane = tid & 31, wid = tid >> 5;
    int i = blockIdx.x * 1024 + tid;
    int v = (i < NN) ? g_cnt[i] : 0;
    int x = v;
#pragma unroll
    for (int o = 1; o < 32; o <<= 1) {
        int y = __shfl_up_sync(0xffffffffu, x, o);
        if (lane >= o) x += y;
    }
    if (lane == 31) warp_sums[wid] = x;
    __syncthreads();
    if (wid == 0) {
        int ws = warp_sums[lane];
#pragma unroll
        for (int o = 1; o < 32; o <<= 1) {
            int y = __shfl_up_sync(0xffffffffu, ws, o);
            if (lane >= o) ws += y;
        }
        warp_sums[lane] = ws;
    }
    __syncthreads();
    int incl = x + (wid ? warp_sums[wid - 1] : 0);
    if (i < NN) {
        g_off[i] = incl - v;
        g_dinv[i] = rsqrtf((float)v + 1.0f);
    }
    if (tid == 1023) g_bsum[blockIdx.x] = incl;
}
// scan of block totals folded in: each 256-node block adds its scan1-block prefix
__global__ void k_scan3(int nblk) {
    __shared__ int sb[64];
    __shared__ int prefix;
    int tid = threadIdx.x;
    if (tid < 64) sb[tid] = (tid < nblk) ? g_bsum[tid] : 0;
    __syncthreads();
    if (tid == 0) {
        int need = blockIdx.x >> 2;   // (blockIdx.x*256)/1024
        int s = 0;
        for (int k = 0; k < need; k++) s += sb[k];
        prefix = s;
    }
    __syncthreads();
    int i = blockIdx.x * 256 + tid;
    if (i < NN) {
        int o = g_off[i] + prefix;
        g_off[i] = o;
        g_cur[i] = o;
    }
    if (i == 0) g_off[NN] = NE;
}
__global__ void k_scatter(const int* __restrict__ src, const int* __restrict__ dst) {
    int e = blockIdx.x * blockDim.x + threadIdx.x;
    if (e >= NE) return;
    int pos = atomicAdd(&g_cur[dst[e]], 1);
    g_csrc[pos] = src[e];
}

// ---------------- tensor-core GEMM with fused input-LayerNorm+ReLU ----------------
template <bool LNIN, bool PAIR>
__global__ void __launch_bounds__(256) gemm128t(
        const float* __restrict__ A,
        const __half* __restrict__ Wa16, const float* __restrict__ ba, __half* __restrict__ houta,
        const __half* __restrict__ Wb16, const float* __restrict__ bb, float* __restrict__ foutb,
        int slot, const float* __restrict__ gm, const float* __restrict__ bt) {
    extern __shared__ char smem[];
    __half (*Ah)[136]  = (__half(*)[136])smem;
    __half (*Wsh)[136] = (__half(*)[136])(smem + 34816);

    bool second = PAIR && (blockIdx.y != 0);
    const __half* W16  = second ? Wb16 : Wa16;
    const float*  bias = second ? bb : ba;

    int t = threadIdx.x;
    int row0 = blockIdx.x * 128;

    float fmu = 0.f, finv = 0.f;
    if (LNIN) {
        double mu = g_red[2 * slot] * (1.0 / (double)ND);
        double var = g_red[2 * slot + 1] * (1.0 / (double)ND) - mu * mu;
        fmu = (float)mu;
        finv = 1.0f / (sqrtf(fmaxf((float)var, 0.0f)) + EPSF);
    }

#pragma unroll
    for (int j = 0; j < 8; j++) {
        int u = t + j * 256;
        int lin = u * 8;
        int r = lin >> 7, c = lin & 127;
        *(uint4*)&Wsh[r][c] = *(const uint4*)(W16 + (size_t)r * 128 + c);
    }
#pragma unroll
    for (int j = 0; j < 16; j++) {
        int f = t + j * 256;
        int lin = f * 4;
        int r = lin >> 7, c = lin & 127;
        int gr = row0 + r;
        float4 v = (gr < NN) ? *(const float4*)(A + (size_t)gr * 128 + c)
                             : make_float4(0.f, 0.f, 0.f, 0.f);
        if (LNIN) {
            float4 gv = *(const float4*)(gm + c);
            float4 bv = *(const float4*)(bt + c);
            v.x = fmaxf((v.x - fmu) * finv * gv.x + bv.x, 0.f);
            v.y = fmaxf((v.y - fmu) * finv * gv.y + bv.y, 0.f);
            v.z = fmaxf((v.z - fmu) * finv * gv.z + bv.z, 0.f);
            v.w = fmaxf((v.w - fmu) * finv * gv.w + bv.w, 0.f);
        }
        __half2* dsth = (__half2*)&Ah[r][c];
        dsth[0] = __floats2half2_rn(v.x, v.y);
        dsth[1] = __floats2half2_rn(v.z, v.w);
    }
    __syncthreads();

    int w = t >> 5;
    int lane = t & 31;

    wmma::fragment<wmma::accumulator, 16, 16, 16, float> acc[8];
#pragma unroll
    for (int n = 0; n < 8; n++) wmma::fill_fragment(acc[n], 0.0f);

#pragma unroll
    for (int k = 0; k < 8; k++) {
        wmma::fragment<wmma::matrix_a, 16, 16, 16, __half, wmma::row_major> af;
        wmma::load_matrix_sync(af, &Ah[w * 16][k * 16], 136);
#pragma unroll
        for (int n = 0; n < 8; n++) {
            wmma::fragment<wmma::matrix_b, 16, 16, 16, __half, wmma::row_major> bf;
            wmma::load_matrix_sync(bf, &Wsh[k * 16][n * 16], 136);
            wmma::mma_sync(acc[n], af, bf, acc[n]);
        }
    }
    __syncthreads();

    float* stage = (float*)smem + (size_t)w * (16 * 136);
#pragma unroll
    for (int n = 0; n < 8; n++)
        wmma::store_matrix_sync(stage + n * 16, acc[n], 136, wmma::mem_row_major);
    __syncwarp();

    int row_in = lane >> 1;
    int c0 = (lane & 1) * 64;
    int gr = row0 + w * 16 + row_in;
    if (gr < NN) {
#pragma unroll
        for (int q = 0; q < 64; q += 8) {
            int colg = c0 + q;
            float4 v0 = *(float4*)(stage + row_in * 136 + colg);
            float4 v1 = *(float4*)(stage + row_in * 136 + colg + 4);
            if (bias) {
                float4 b0 = *(const float4*)(bias + colg);
                float4 b1 = *(const float4*)(bias + colg + 4);
                v0.x += b0.x; v0.y += b0.y; v0.z += b0.z; v0.w += b0.w;
                v1.x += b1.x; v1.y += b1.y; v1.z += b1.z; v1.w += b1.w;
            }
            if (second) {
                float* o = foutb + (size_t)gr * 128 + colg;
                *(float4*)(o)     = v0;
                *(float4*)(o + 4) = v1;
            } else {
                __half2 hh[4];
                hh[0] = __floats2half2_rn(v0.x, v0.y);
                hh[1] = __floats2half2_rn(v0.z, v0.w);
                hh[2] = __floats2half2_rn(v1.x, v1.y);
                hh[3] = __floats2half2_rn(v1.z, v1.w);
                *(uint4*)(houta + (size_t)gr * 128 + colg) = *(uint4*)hh;
            }
        }
    }
}

// ---------------- block epilogue: fused LN partial reduction ----------------
__device__ __forceinline__ void ln_block_reduce(float s, float s2, int slot) {
#pragma unroll
    for (int o = 16; o; o >>= 1) {
        s  += __shfl_xor_sync(0xffffffffu, s, o);
        s2 += __shfl_xor_sync(0xffffffffu, s2, o);
    }
    __shared__ float shs[8], shs2[8];
    int wid = threadIdx.x >> 5, lane = threadIdx.x & 31;
    if (lane == 0) { shs[wid] = s; shs2[wid] = s2; }
    __syncthreads();
    if (threadIdx.x == 0) {
        double ts = 0.0, t2 = 0.0;
        int nw = blockDim.x >> 5;
        for (int k = 0; k < nw; k++) { ts += (double)shs[k]; t2 += (double)shs2[k]; }
        atomicAdd(&g_red[2 * slot], ts);
        atomicAdd(&g_red[2 * slot + 1], t2);
    }
}

// ---------------- GCN aggregation (CSR gather, warp/node, chunk-8, f32x2) ------
__global__ void __launch_bounds__(256) k_gcn_csr(const float* __restrict__ bias, int slot) {
    int w = (blockIdx.x * blockDim.x + threadIdx.x) >> 5;
    int lane = threadIdx.x & 31;
    float s = 0.f, s2 = 0.f;
    if (w < NN) {
        float dd = g_dinv[w];
        uint2 rawS = *(const uint2*)(g_xwh + (size_t)w * 128 + lane * 4);
        ull v01, v23;
        h4_to_2x2(rawS, v01, v23);
        float sf = dd * dd;
        ull sf2 = pk2(sf, sf);
        ull a01 = mul2p(v01, sf2);
        ull a23 = mul2p(v23, sf2);
        int b = g_off[w], e = g_off[w + 1];
        int i = b;
        for (; i + 8 <= e; i += 8) {
            int si[8];
#pragma unroll
            for (int j = 0; j < 8; j++) si[j] = g_csrc[i + j];
            uint2 raw[8];
#pragma unroll
            for (int j = 0; j < 8; j++)
                raw[j] = *(const uint2*)(g_xwh + (size_t)si[j] * 128 + lane * 4);
#pragma unroll
            for (int j = 0; j < 8; j++) {
                float nr = g_dinv[si[j]] * dd;
                ull nr2 = pk2(nr, nr);
                ull u01, u23;
                h4_to_2x2(raw[j], u01, u23);
                a01 = fma2(u01, nr2, a01);
                a23 = fma2(u23, nr2, a23);
            }
        }
        for (; i < e; i++) {
            int sn = g_csrc[i];
            float nr = g_dinv[sn] * dd;
            ull nr2 = pk2(nr, nr);
            uint2 rw = *(const uint2*)(g_xwh + (size_t)sn * 128 + lane * 4);
            ull u01, u23;
            h4_to_2x2(rw, u01, u23);
            a01 = fma2(u01, nr2, a01);
            a23 = fma2(u23, nr2, a23);
        }
        float4 b4 = ((const float4*)bias)[lane];
        float ax, ay, az, aw;
        upk2(a01, ax, ay); upk2(a23, az, aw);
        ax += b4.x; ay += b4.y; az += b4.z; aw += b4.w;
        ((float4*)(g_acc + (size_t)w * 128))[lane] = make_float4(ax, ay, az, aw);
        s  = ax + ay + az + aw;
        s2 = ax * ax + ay * ay + az * az + aw * aw;
    }
    ln_block_reduce(s, s2, slot);
}

// ---------------- fused GATv2 (CSR gather + online softmax, chunk-4, f32x2) ----
// leaky_relu(v) = 0.6v + 0.4|v|  for slope 0.2
#define C06 0x3F19999A3F19999AULL   // (0.6f,0.6f)
#define C04 0x3ECCCCCD3ECCCCCDULL   // (0.4f,0.4f)

template <int H>
__device__ __forceinline__ float score2(ull l01, ull l23, ull r01, ull r23,
                                        ull a01, ull a23) {
    ull s01 = add2p(l01, r01), s23 = add2p(l23, r23);
    ull b01 = abs2p(s01),      b23 = abs2p(s23);
    ull t01 = fma2(b01, C04, mul2p(s01, C06));
    ull t23 = fma2(b23, C04, mul2p(s23, C06));
    ull qp  = fma2(t23, a23, mul2p(t01, a01));
    float qa, qb;
    upk2(qp, qa, qb);
    float q = qa + qb;
    if (H == 8) {
        q += __shfl_xor_sync(0xffffffffu, q, 1);
        q += __shfl_xor_sync(0xffffffffu, q, 2);
    } else {
#pragma unroll
        for (int o = 16; o; o >>= 1) q += __shfl_xor_sync(0xffffffffu, q, o);
    }
    return q;
}

template <int H>
__global__ void __launch_bounds__(256) k_gat_csr(const float* __restrict__ att,
                                                 const float* __restrict__ bias, int slot) {
    int w = (blockIdx.x * blockDim.x + threadIdx.x) >> 5;
    int lane = threadIdx.x & 31;
    float ps = 0.f, ps2 = 0.f;
    if (w < NN) {
        float4 r4 = ((const float4*)(g_xr + (size_t)w * 128))[lane];
        float4 a4 = ((const float4*)att)[lane];
        ull r01 = pk2(r4.x, r4.y), r23 = pk2(r4.z, r4.w);
        ull a01 = pk2(a4.x, a4.y), a23 = pk2(a4.z, a4.w);

        uint2 rawl = *(const uint2*)(g_xlh + (size_t)w * 128 + lane * 4);
        ull l01, l23;
        h4_to_2x2(rawl, l01, l23);
        float m = score2<H>(l01, l23, r01, r23, a01, a23);
        float den = 1.0f;
        ull acc01 = l01, acc23 = l23;

        int b = g_off[w], e = g_off[w + 1];
        int i = b;
        for (; i + 4 <= e; i += 4) {
            int s0 = g_csrc[i], s1 = g_csrc[i + 1], s2 = g_csrc[i + 2], s3 = g_csrc[i + 3];
            uint2 w0r = *(const uint2*)(g_xlh + (size_t)s0 * 128 + lane * 4);
            uint2 w1r = *(const uint2*)(g_xlh + (size_t)s1 * 128 + lane * 4);
            uint2 w2r = *(const uint2*)(g_xlh + (size_t)s2 * 128 + lane * 4);
            uint2 w3r = *(const uint2*)(g_xlh + (size_t)s3 * 128 + lane * 4);
            ull u0a, u0b, u1a, u1b, u2a, u2b, u3a, u3b;
            h4_to_2x2(w0r, u0a, u0b);
            h4_to_2x2(w1r, u1a, u1b);
            h4_to_2x2(w2r, u2a, u2b);
            h4_to_2x2(w3r, u3a, u3b);
            float q0 = score2<H>(u0a, u0b, r01, r23, a01, a23);
            float q1 = score2<H>(u1a, u1b, r01, r23, a01, a23);
            float q2 = score2<H>(u2a, u2b, r01, r23, a01, a23);
            float q3 = score2<H>(u3a, u3b, r01, r23, a01, a23);
            float nm = fmaxf(fmaxf(fmaxf(q0, q1), fmaxf(q2, q3)), m);
            float so = __expf(m - nm);
            float w0 = __expf(q0 - nm), w1 = __expf(q1 - nm);
            float w2 = __expf(q2 - nm), w3 = __expf(q3 - nm);
            den = den * so + w0 + w1 + w2 + w3;
            ull so2 = pk2(so, so);
            ull w0p = pk2(w0, w0), w1p = pk2(w1, w1);
            ull w2p = pk2(w2, w2), w3p = pk2(w3, w3);
            acc01 = mul2p(acc01, so2);
            acc01 = fma2(u0a, w0p, acc01);
            acc01 = fma2(u1a, w1p, acc01);
            acc01 = fma2(u2a, w2p, acc01);
            acc01 = fma2(u3a, w3p, acc01);
            acc23 = mul2p(acc23, so2);
            acc23 = fma2(u0b, w0p, acc23);
            acc23 = fma2(u1b, w1p, acc23);
            acc23 = fma2(u2b, w2p, acc23);
            acc23 = fma2(u3b, w3p, acc23);
            m = nm;
        }
        for (; i < e; i++) {
            int sn = g_csrc[i];
            uint2 vr = *(const uint2*)(g_xlh + (size_t)sn * 128 + lane * 4);
            ull ua, ub;
            h4_to_2x2(vr, ua, ub);
            float q = score2<H>(ua, ub, r01, r23, a01, a23);
            float nm = fmaxf(m, q);
            float so = __expf(m - nm);
            float wg = __expf(q - nm);
            den = den * so + wg;
            ull so2 = pk2(so, so), wg2 = pk2(wg, wg);
            acc01 = fma2(ua, wg2, mul2p(acc01, so2));
            acc23 = fma2(ub, wg2, mul2p(acc23, so2));
            m = nm;
        }
        float inv = 1.0f / den;
        float4 b4 = ((const float4*)bias)[lane];
        float ax, ay, az, aw;
        upk2(acc01, ax, ay); upk2(acc23, az, aw);
        ax = ax * inv + b4.x;
        ay = ay * inv + b4.y;
        az = az * inv + b4.z;
        aw = aw * inv + b4.w;
        ((float4*)(g_acc + (size_t)w * 128))[lane] = make_float4(ax, ay, az, aw);
        ps  = ax + ay + az + aw;
        ps2 = ax * ax + ay * ay + az * az + aw * aw;
    }
    ln_block_reduce(ps, ps2, slot);
}

// ---------------- LayerNorm apply (final layer only) ----------------
__global__ void k_ln_apply(const float* __restrict__ in,
                           const float* __restrict__ gm, const float* __restrict__ bt,
                           float* __restrict__ out, int slot) {
    int i = blockIdx.x * blockDim.x + threadIdx.x;
    if (i >= ND) return;
    double mu = g_red[2 * slot] * (1.0 / (double)ND);
    double var = g_red[2 * slot + 1] * (1.0 / (double)ND) - mu * mu;
    float inv = 1.0f / (sqrtf(fmaxf((float)var, 0.0f)) + EPSF);
    int c = i & 127;
    float v = in[i];
    out[i] = (v - (float)mu) * inv * gm[c] + bt[c];
}

// ---------------- launch ----------------
static inline int gridFor(long long n, int blk) { return (int)((n + blk - 1) / blk); }

extern "C" void kernel_launch(void* const* d_in, const int* in_sizes, int n_in,
                              void* d_out, int out_size) {
    const float* x   = (const float*)d_in[0];
    const int*   ei  = (const int*)d_in[1];
    const float* W0  = (const float*)d_in[2];
    const float* b0  = (const float*)d_in[3];
    const float* g0  = (const float*)d_in[4];
    const float* be0 = (const float*)d_in[5];
    const float* Wl1 = (const float*)d_in[6];
    const float* bl1 = (const float*)d_in[7];
    const float* Wr1 = (const float*)d_in[8];
    const float* br1 = (const float*)d_in[9];
    const float* att1= (const float*)d_in[10];
    const float* bg1 = (const float*)d_in[11];
    const float* g1  = (const float*)d_in[12];
    const float* be1 = (const float*)d_in[13];
    const float* W2  = (const float*)d_in[14];
    const float* b2  = (const float*)d_in[15];
    const float* g2  = (const float*)d_in[16];
    const float* be2 = (const float*)d_in[17];
    const float* Wl3 = (const float*)d_in[18];
    const float* bl3 = (const float*)d_in[19];
    const float* Wr3 = (const float*)d_in[20];
    const float* br3 = (const float*)d_in[21];
    const float* att3= (const float*)d_in[22];
    const float* bg3 = (const float*)d_in[23];
    const float* g3  = (const float*)d_in[24];
    const float* be3 = (const float*)d_in[25];
    float* out = (float*)d_out;

    const int* src = ei;
    const int* dst = ei + NE;

    const int BLK = 256;
    const int gE   = gridFor(NE, BLK);
    const int gND  = gridFor(ND, BLK);
    const int gNW  = gridFor((long long)NN * 32, BLK);
    const int nGemmX = gridFor(NN, 128);
    const dim3 gG1(nGemmX, 1), gG2(nGemmX, 2);
    const int nScanBlk = gridFor(NN, 1024);
    const int gInit = gridFor(6 * DD * DD, BLK);   // 98304 covers NN too
    const int gN256 = gridFor(NN, 256);

    __half* p_xwh; cudaGetSymbolAddress((void**)&p_xwh, g_xwh);
    __half* p_xlh; cudaGetSymbolAddress((void**)&p_xlh, g_xlh);
    float* p_xr;  cudaGetSymbolAddress((void**)&p_xr, g_xr);
    float* p_acc; cudaGetSymbolAddress((void**)&p_acc, g_acc);
    __half* p_wh; cudaGetSymbolAddress((void**)&p_wh, g_wh);

    const __half* w0h  = p_wh;
    const __half* wl1h = p_wh + 1 * DD * DD;
    const __half* wr1h = p_wh + 2 * DD * DD;
    const __half* w2h  = p_wh + 3 * DD * DD;
    const __half* wl3h = p_wh + 4 * DD * DD;
    const __half* wr3h = p_wh + 5 * DD * DD;

    static bool attr_done = false;
    if (!attr_done) {
        cudaFuncSetAttribute(gemm128t<false, false>,
                             cudaFuncAttributeMaxDynamicSharedMemorySize, GEMM_SMEM);
        cudaFuncSetAttribute(gemm128t<true, false>,
                             cudaFuncAttributeMaxDynamicSharedMemorySize, GEMM_SMEM);
        cudaFuncSetAttribute(gemm128t<true, true>,
                             cudaFuncAttributeMaxDynamicSharedMemorySize, GEMM_SMEM);
        attr_done = true;
    }

    // CSR front; launch #4 = gemm0 (ncu capture slot)
    k_init<<<gInit, BLK>>>(W0, Wl1, Wr1, W2, Wl3, Wr3);
    k_hist<<<gE, BLK>>>(dst);
    k_scan1<<<nScanBlk, 1024>>>();
    gemm128t<false, false><<<gG1, BLK, GEMM_SMEM>>>(x, w0h, nullptr, p_xwh,
                                                    nullptr, nullptr, nullptr, 0, nullptr, nullptr);
    k_scan3<<<gN256, 256>>>(nScanBlk);
    k_scatter<<<gE, BLK>>>(src, dst);

    // ---- layer 0: GCN agg ----
    k_gcn_csr<<<gNW, BLK>>>(b0, 0);

    // ---- layer 1: GATv2 (H=8) ----
    gemm128t<true, true><<<gG2, BLK, GEMM_SMEM>>>(p_acc, wl1h, bl1, p_xlh,
                                                  wr1h, br1, p_xr, 0, g0, be0);
    k_gat_csr<8><<<gNW, BLK>>>(att1, bg1, 1);

    // ---- layer 2: GCN ----
    gemm128t<true, false><<<gG1, BLK, GEMM_SMEM>>>(p_acc, w2h, nullptr, p_xwh,
                                                   nullptr, nullptr, nullptr, 1, g1, be1);
    k_gcn_csr<<<gNW, BLK>>>(b2, 2);

    // ---- layer 3: GATv2 (H=1) ----
    gemm128t<true, true><<<gG2, BLK, GEMM_SMEM>>>(p_acc, wl3h, bl3, p_xlh,
                                                  wr3h, br3, p_xr, 2, g2, be2);
    k_gat_csr<1><<<gNW, BLK>>>(att3, bg3, 3);

    // ---- final LN -> output ----
    k_ln_apply<<<gND, BLK>>>(p_acc, g3, be3, out, 3);
}